// round 1
// baseline (speedup 1.0000x reference)
#include <cuda_runtime.h>
#include <math.h>

// Problem dims (fixed)
#define BATCH   16
#define SEQ     512
#define DMODEL  1024
#define NHEAD   16
#define DK      64
#define FFN_DIM 4096
#define ROWS    (BATCH * SEQ)        // 8192

// ---------------- scratch (device globals; no allocation) ----------------
__device__ float g_h  [ROWS * DMODEL];   // LN output (reused for LN2)
__device__ float g_q  [ROWS * DMODEL];
__device__ float g_k  [ROWS * DMODEL];
__device__ float g_v  [ROWS * DMODEL];
__device__ float g_att[ROWS * DMODEL];
__device__ float g_x1 [ROWS * DMODEL];   // x + attn sublayer
__device__ float g_ffn[ROWS * FFN_DIM];

// ---------------- LayerNorm: one block per row ----------------
__global__ void ln_kernel(const float* __restrict__ x,
                          const float* __restrict__ g,
                          const float* __restrict__ b,
                          float* __restrict__ out)
{
    int row = blockIdx.x;
    const float4* xr = reinterpret_cast<const float4*>(x + (size_t)row * DMODEL);
    int t = threadIdx.x;                  // 256 threads, 256 float4 per row
    float4 v = xr[t];
    float s  = v.x + v.y + v.z + v.w;
    float sq = v.x*v.x + v.y*v.y + v.z*v.z + v.w*v.w;

    // block reduce (8 warps)
    __shared__ float red_s[8], red_q[8];
    for (int o = 16; o > 0; o >>= 1) {
        s  += __shfl_xor_sync(0xffffffffu, s,  o);
        sq += __shfl_xor_sync(0xffffffffu, sq, o);
    }
    int wid = t >> 5, lid = t & 31;
    if (lid == 0) { red_s[wid] = s; red_q[wid] = sq; }
    __syncthreads();
    if (wid == 0) {
        float ss = (lid < 8) ? red_s[lid] : 0.f;
        float qq = (lid < 8) ? red_q[lid] : 0.f;
        for (int o = 4; o > 0; o >>= 1) {
            ss += __shfl_xor_sync(0xffffffffu, ss, o);
            qq += __shfl_xor_sync(0xffffffffu, qq, o);
        }
        if (lid == 0) { red_s[0] = ss; red_q[0] = qq; }
    }
    __syncthreads();
    float mean = red_s[0] * (1.0f / DMODEL);
    float var  = red_q[0] * (1.0f / DMODEL) - mean * mean;
    float rstd = rsqrtf(var + 1e-5f);

    const float4* gr = reinterpret_cast<const float4*>(g);
    const float4* br = reinterpret_cast<const float4*>(b);
    float4 gv = gr[t], bv = br[t];
    float4 o4;
    o4.x = (v.x - mean) * rstd * gv.x + bv.x;
    o4.y = (v.y - mean) * rstd * gv.y + bv.y;
    o4.z = (v.z - mean) * rstd * gv.z + bv.z;
    o4.w = (v.w - mean) * rstd * gv.w + bv.w;
    reinterpret_cast<float4*>(out + (size_t)row * DMODEL)[t] = o4;
}

// ---------------- fp32 tiled GEMM: C = A[M,K] @ B[K,N] (+epilogue) ----------------
// EPI: 0 = none, 1 = +bias +resid, 2 = +bias then exact GELU
#define BM 128
#define BN 128
#define BKK 16
#define TM 8
#define TN 8

__device__ __forceinline__ float gelu_exact(float v) {
    return 0.5f * v * (1.0f + erff(v * 0.70710678118654752f));
}

template<int EPI>
__global__ __launch_bounds__(256, 2)
void gemm_kernel(const float* __restrict__ A, const float* __restrict__ B,
                 const float* __restrict__ bias, const float* __restrict__ resid,
                 float* __restrict__ C, int M, int N, int K)
{
    __shared__ float As[BKK][BM + 4];   // A transposed: As[k][m]
    __shared__ float Bs[BKK][BN + 4];

    int tid = threadIdx.x;
    int tx = tid & 15;           // 0..15 -> N
    int ty = tid >> 4;           // 0..15 -> M
    int row0 = blockIdx.y * BM;
    int col0 = blockIdx.x * BN;

    // load mappings
    int ar = tid >> 2;               // 0..63
    int ac = (tid & 3) * 4;          // 0,4,8,12
    int br = tid >> 5;               // 0..7
    int bc = (tid & 31) * 4;         // 0..124

    float acc[TM][TN];
    #pragma unroll
    for (int i = 0; i < TM; i++)
        #pragma unroll
        for (int j = 0; j < TN; j++) acc[i][j] = 0.f;

    for (int k0 = 0; k0 < K; k0 += BKK) {
        #pragma unroll
        for (int i = 0; i < 2; i++) {
            float4 va = *reinterpret_cast<const float4*>(
                &A[(size_t)(row0 + ar + 64*i) * K + k0 + ac]);
            As[ac+0][ar + 64*i] = va.x;
            As[ac+1][ar + 64*i] = va.y;
            As[ac+2][ar + 64*i] = va.z;
            As[ac+3][ar + 64*i] = va.w;
        }
        #pragma unroll
        for (int i = 0; i < 2; i++) {
            float4 vb = *reinterpret_cast<const float4*>(
                &B[(size_t)(k0 + br + 8*i) * N + col0 + bc]);
            *reinterpret_cast<float4*>(&Bs[br + 8*i][bc]) = vb;
        }
        __syncthreads();

        #pragma unroll
        for (int kk = 0; kk < BKK; kk++) {
            float a[TM], b[TN];
            *reinterpret_cast<float4*>(&a[0]) = *reinterpret_cast<const float4*>(&As[kk][ty*TM]);
            *reinterpret_cast<float4*>(&a[4]) = *reinterpret_cast<const float4*>(&As[kk][ty*TM + 4]);
            *reinterpret_cast<float4*>(&b[0]) = *reinterpret_cast<const float4*>(&Bs[kk][tx*TN]);
            *reinterpret_cast<float4*>(&b[4]) = *reinterpret_cast<const float4*>(&Bs[kk][tx*TN + 4]);
            #pragma unroll
            for (int i = 0; i < TM; i++)
                #pragma unroll
                for (int j = 0; j < TN; j++)
                    acc[i][j] += a[i] * b[j];
        }
        __syncthreads();
    }

    // epilogue: each thread owns 8 rows x 8 consecutive cols
    int ccol = col0 + tx * TN;
    float bv[TN];
    if (EPI >= 1) {
        #pragma unroll
        for (int j = 0; j < TN; j++) bv[j] = __ldg(&bias[ccol + j]);
    }
    #pragma unroll
    for (int i = 0; i < TM; i++) {
        int crow = row0 + ty * TM + i;
        float o[TN];
        #pragma unroll
        for (int j = 0; j < TN; j++) o[j] = acc[i][j];
        if (EPI >= 1) {
            #pragma unroll
            for (int j = 0; j < TN; j++) o[j] += bv[j];
        }
        if (EPI == 1) {
            float4 r0 = *reinterpret_cast<const float4*>(&resid[(size_t)crow * N + ccol]);
            float4 r1 = *reinterpret_cast<const float4*>(&resid[(size_t)crow * N + ccol + 4]);
            o[0]+=r0.x; o[1]+=r0.y; o[2]+=r0.z; o[3]+=r0.w;
            o[4]+=r1.x; o[5]+=r1.y; o[6]+=r1.z; o[7]+=r1.w;
        }
        if (EPI == 2) {
            #pragma unroll
            for (int j = 0; j < TN; j++) o[j] = gelu_exact(o[j]);
        }
        *reinterpret_cast<float4*>(&C[(size_t)crow * N + ccol])     = make_float4(o[0],o[1],o[2],o[3]);
        *reinterpret_cast<float4*>(&C[(size_t)crow * N + ccol + 4]) = make_float4(o[4],o[5],o[6],o[7]);
    }
}

// ---------------- causal flash attention ----------------
// grid: (8 q-tiles, 256 bh), 256 threads. 64x64 tiles, Dk=64.
// thread t: row r = t>>2, column group cg = t&3 (16 cols each).
#define AT_PAD 68
#define ATT_SMEM (4 * 64 * AT_PAD * (int)sizeof(float))   // Qs,Ks,Vs,Ss

__global__ void attn_kernel(const float* __restrict__ Q,
                            const float* __restrict__ K,
                            const float* __restrict__ V,
                            float* __restrict__ O)
{
    extern __shared__ float sm[];
    float* Qs = sm;
    float* Ks = Qs + 64 * AT_PAD;
    float* Vs = Ks + 64 * AT_PAD;
    float* Ss = Vs + 64 * AT_PAD;

    int tid = threadIdx.x;
    int bh = blockIdx.y;
    int b = bh >> 4, h = bh & 15;
    int qt = blockIdx.x;

    const float* qbase = Q + ((size_t)(b * SEQ + qt * 64)) * DMODEL + h * DK;

    // load Q tile (64 rows x 64 cols)
    for (int i = tid; i < 64 * 16; i += 256) {
        int row = i >> 4, c4 = (i & 15) * 4;
        float4 v = *reinterpret_cast<const float4*>(qbase + (size_t)row * DMODEL + c4);
        float* d = &Qs[row * AT_PAD + c4];
        d[0] = v.x; d[1] = v.y; d[2] = v.z; d[3] = v.w;
    }

    int r  = tid >> 2;
    int cg = tid & 3;
    int q_global = qt * 64 + r;

    float acc[16];
    #pragma unroll
    for (int i = 0; i < 16; i++) acc[i] = 0.f;
    float m_old = -INFINITY, l = 0.f;

    for (int kt = 0; kt <= qt; kt++) {
        __syncthreads();   // protect Ks/Vs/Ss reuse from previous iter
        const float* kbase = K + ((size_t)(b * SEQ + kt * 64)) * DMODEL + h * DK;
        const float* vbase = V + ((size_t)(b * SEQ + kt * 64)) * DMODEL + h * DK;
        for (int i = tid; i < 64 * 16; i += 256) {
            int row = i >> 4, c4 = (i & 15) * 4;
            float4 vk = *reinterpret_cast<const float4*>(kbase + (size_t)row * DMODEL + c4);
            float* dk = &Ks[row * AT_PAD + c4];
            dk[0] = vk.x; dk[1] = vk.y; dk[2] = vk.z; dk[3] = vk.w;
            float4 vv = *reinterpret_cast<const float4*>(vbase + (size_t)row * DMODEL + c4);
            float* dv = &Vs[row * AT_PAD + c4];
            dv[0] = vv.x; dv[1] = vv.y; dv[2] = vv.z; dv[3] = vv.w;
        }
        __syncthreads();

        // scores for the 16 key columns this thread owns
        float s[16];
        const float* qr = &Qs[r * AT_PAD];
        #pragma unroll
        for (int jj = 0; jj < 16; jj++) {
            int j = cg * 16 + jj;
            const float* kr = &Ks[j * AT_PAD];
            float a = 0.f;
            #pragma unroll
            for (int d = 0; d < 64; d++) a += qr[d] * kr[d];
            int k_global = kt * 64 + j;
            s[jj] = (k_global <= q_global) ? a * 0.125f : -INFINITY;
        }

        float tm = s[0];
        #pragma unroll
        for (int jj = 1; jj < 16; jj++) tm = fmaxf(tm, s[jj]);
        tm = fmaxf(tm, __shfl_xor_sync(0xffffffffu, tm, 1));
        tm = fmaxf(tm, __shfl_xor_sync(0xffffffffu, tm, 2));

        float m_new = fmaxf(m_old, tm);      // finite after kt=0 (j=0 always valid)
        float alpha = __expf(m_old - m_new); // -inf -> 0 on first tile

        float psum = 0.f;
        #pragma unroll
        for (int jj = 0; jj < 16; jj++) {
            float p = __expf(s[jj] - m_new);
            Ss[r * AT_PAD + cg * 16 + jj] = p;
            psum += p;
        }
        psum += __shfl_xor_sync(0xffffffffu, psum, 1);
        psum += __shfl_xor_sync(0xffffffffu, psum, 2);

        l = l * alpha + psum;
        m_old = m_new;
        #pragma unroll
        for (int i = 0; i < 16; i++) acc[i] *= alpha;

        __syncthreads();   // Ss complete

        // acc[c] += sum_j P[r][j] * V[j][cg*16+c]
        for (int j = 0; j < 64; j++) {
            float p = Ss[r * AT_PAD + j];
            const float* vr = &Vs[j * AT_PAD + cg * 16];
            #pragma unroll
            for (int c = 0; c < 16; c++) acc[c] += p * vr[c];
        }
    }

    float inv = 1.0f / l;
    float* obase = O + ((size_t)(b * SEQ + q_global)) * DMODEL + h * DK + cg * 16;
    #pragma unroll
    for (int c = 0; c < 16; c += 4) {
        float4 v = make_float4(acc[c]*inv, acc[c+1]*inv, acc[c+2]*inv, acc[c+3]*inv);
        *reinterpret_cast<float4*>(obase + c) = v;
    }
}

// ---------------- launch ----------------
extern "C" void kernel_launch(void* const* d_in, const int* in_sizes, int n_in,
                              void* d_out, int out_size)
{
    const float* x     = (const float*)d_in[0];
    const float* ln1_g = (const float*)d_in[1];
    const float* ln1_b = (const float*)d_in[2];
    const float* w_q   = (const float*)d_in[3];
    const float* w_k   = (const float*)d_in[4];
    const float* w_v   = (const float*)d_in[5];
    const float* w_o   = (const float*)d_in[6];
    const float* b_o   = (const float*)d_in[7];
    const float* ln2_g = (const float*)d_in[8];
    const float* ln2_b = (const float*)d_in[9];
    const float* w1    = (const float*)d_in[10];
    const float* b1    = (const float*)d_in[11];
    const float* w2    = (const float*)d_in[12];
    const float* b2    = (const float*)d_in[13];
    float* out = (float*)d_out;

    float *h, *q, *k, *v, *att, *x1, *ffn;
    cudaGetSymbolAddress((void**)&h,   g_h);
    cudaGetSymbolAddress((void**)&q,   g_q);
    cudaGetSymbolAddress((void**)&k,   g_k);
    cudaGetSymbolAddress((void**)&v,   g_v);
    cudaGetSymbolAddress((void**)&att, g_att);
    cudaGetSymbolAddress((void**)&x1,  g_x1);
    cudaGetSymbolAddress((void**)&ffn, g_ffn);

    cudaFuncSetAttribute(attn_kernel, cudaFuncAttributeMaxDynamicSharedMemorySize, ATT_SMEM);

    dim3 gP(DMODEL / BN, ROWS / BM);     // (8, 64)
    dim3 gF1(FFN_DIM / BN, ROWS / BM);   // (32, 64)

    // 1) LN1
    ln_kernel<<<ROWS, 256>>>(x, ln1_g, ln1_b, h);
    // 2) QKV projections
    gemm_kernel<0><<<gP, 256>>>(h, w_q, nullptr, nullptr, q, ROWS, DMODEL, DMODEL);
    gemm_kernel<0><<<gP, 256>>>(h, w_k, nullptr, nullptr, k, ROWS, DMODEL, DMODEL);
    gemm_kernel<0><<<gP, 256>>>(h, w_v, nullptr, nullptr, v, ROWS, DMODEL, DMODEL);
    // 3) causal attention
    attn_kernel<<<dim3(SEQ / 64, BATCH * NHEAD), 256, ATT_SMEM>>>(q, k, v, att);
    // 4) output projection + bias + residual
    gemm_kernel<1><<<gP, 256>>>(att, w_o, b_o, x, x1, ROWS, DMODEL, DMODEL);
    // 5) LN2
    ln_kernel<<<ROWS, 256>>>(x1, ln2_g, ln2_b, h);
    // 6) FFN up + GELU
    gemm_kernel<2><<<gF1, 256>>>(h, w1, b1, nullptr, ffn, ROWS, FFN_DIM, DMODEL);
    // 7) FFN down + bias + residual -> out
    gemm_kernel<1><<<gP, 256>>>(ffn, w2, b2, x1, out, ROWS, DMODEL, FFN_DIM);
}

// round 3
// speedup vs baseline: 1.9114x; 1.9114x over previous
#include <cuda_runtime.h>
#include <cuda_bf16.h>
#include <math.h>
#include <stdint.h>

#define BATCH   16
#define SEQ     512
#define DMODEL  1024
#define NHEAD   16
#define DK      64
#define FFN_DIM 4096
#define ROWS    (BATCH * SEQ)        // 8192

// ---------------- scratch (device globals; no allocation) ----------------
__device__ __nv_bfloat16 g_hhi [ROWS * DMODEL];
__device__ __nv_bfloat16 g_hlo [ROWS * DMODEL];
__device__ float g_q  [ROWS * DMODEL];
__device__ float g_k  [ROWS * DMODEL];
__device__ float g_v  [ROWS * DMODEL];
__device__ __nv_bfloat16 g_atthi[ROWS * DMODEL];
__device__ __nv_bfloat16 g_attlo[ROWS * DMODEL];
__device__ float g_x1 [ROWS * DMODEL];
__device__ __nv_bfloat16 g_ffnhi[ROWS * FFN_DIM];
__device__ __nv_bfloat16 g_ffnlo[ROWS * FFN_DIM];
// transposed + split weights: T[N,K]
__device__ __nv_bfloat16 g_wqT_hi[DMODEL*DMODEL], g_wqT_lo[DMODEL*DMODEL];
__device__ __nv_bfloat16 g_wkT_hi[DMODEL*DMODEL], g_wkT_lo[DMODEL*DMODEL];
__device__ __nv_bfloat16 g_wvT_hi[DMODEL*DMODEL], g_wvT_lo[DMODEL*DMODEL];
__device__ __nv_bfloat16 g_woT_hi[DMODEL*DMODEL], g_woT_lo[DMODEL*DMODEL];
__device__ __nv_bfloat16 g_w1T_hi[DMODEL*FFN_DIM], g_w1T_lo[DMODEL*FFN_DIM];
__device__ __nv_bfloat16 g_w2T_hi[FFN_DIM*DMODEL], g_w2T_lo[FFN_DIM*DMODEL];

// ---------------- helpers ----------------
__device__ __forceinline__ uint32_t smem_u32(const void* p) {
    uint32_t a;
    asm("{ .reg .u64 t; cvta.to.shared.u64 t, %1; cvt.u32.u64 %0, t; }" : "=r"(a) : "l"(p));
    return a;
}
#define CP_ASYNC16(dst, src) \
    asm volatile("cp.async.cg.shared.global [%0], [%1], 16;" :: "r"(dst), "l"(src) : "memory")
#define CP_COMMIT() asm volatile("cp.async.commit_group;" ::: "memory")
#define CP_WAIT(n)  asm volatile("cp.async.wait_group %0;" :: "n"(n) : "memory")
#define SMEM_SWZ128(off) ((off) ^ (((off) >> 3) & 0x70))

__device__ __forceinline__ void ldsm_x4(uint32_t* r, uint32_t addr) {
    asm volatile("ldmatrix.sync.aligned.m8n8.x4.shared.b16 {%0,%1,%2,%3}, [%4];"
        : "=r"(r[0]), "=r"(r[1]), "=r"(r[2]), "=r"(r[3]) : "r"(addr));
}
__device__ __forceinline__ void mma16816(float* d, const uint32_t* a, const uint32_t* b) {
    asm volatile("mma.sync.aligned.m16n8k16.row.col.f32.bf16.bf16.f32 "
        "{%0,%1,%2,%3}, {%4,%5,%6,%7}, {%8,%9}, {%0,%1,%2,%3};"
        : "+f"(d[0]), "+f"(d[1]), "+f"(d[2]), "+f"(d[3])
        : "r"(a[0]), "r"(a[1]), "r"(a[2]), "r"(a[3]), "r"(b[0]), "r"(b[1]));
}

__device__ __forceinline__ float gelu_exact(float v) {
    return 0.5f * v * (1.0f + erff(v * 0.70710678118654752f));
}
__device__ __forceinline__ void split_bf16(float v, __nv_bfloat16& hi, __nv_bfloat16& lo) {
    hi = __float2bfloat16(v);
    lo = __float2bfloat16(v - __bfloat162float(hi));
}

// ---------------- weight transpose + split: W[K,N] -> T[N,K] hi/lo ----------------
__global__ void wsplitT(const float* __restrict__ W,
                        __nv_bfloat16* __restrict__ Thi,
                        __nv_bfloat16* __restrict__ Tlo, int K, int N)
{
    __shared__ float t[32][33];
    int n0 = blockIdx.x * 32, k0 = blockIdx.y * 32;
    int tx = threadIdx.x, ty = threadIdx.y;
    #pragma unroll
    for (int i = 0; i < 4; i++)
        t[ty + 8*i][tx] = W[(size_t)(k0 + ty + 8*i) * N + n0 + tx];
    __syncthreads();
    #pragma unroll
    for (int i = 0; i < 4; i++) {
        float v = t[tx][ty + 8*i];
        __nv_bfloat16 hi, lo; split_bf16(v, hi, lo);
        size_t o = (size_t)(n0 + ty + 8*i) * K + k0 + tx;
        Thi[o] = hi; Tlo[o] = lo;
    }
}

// ---------------- LayerNorm: one block per row, outputs bf16 hi/lo ----------------
__global__ void ln_kernel(const float* __restrict__ x,
                          const float* __restrict__ g,
                          const float* __restrict__ b,
                          __nv_bfloat16* __restrict__ ohi,
                          __nv_bfloat16* __restrict__ olo)
{
    int row = blockIdx.x;
    const float4* xr = reinterpret_cast<const float4*>(x + (size_t)row * DMODEL);
    int t = threadIdx.x;
    float4 v = xr[t];
    float s  = v.x + v.y + v.z + v.w;
    float sq = v.x*v.x + v.y*v.y + v.z*v.z + v.w*v.w;

    __shared__ float red_s[8], red_q[8];
    for (int o = 16; o > 0; o >>= 1) {
        s  += __shfl_xor_sync(0xffffffffu, s,  o);
        sq += __shfl_xor_sync(0xffffffffu, sq, o);
    }
    int wid = t >> 5, lid = t & 31;
    if (lid == 0) { red_s[wid] = s; red_q[wid] = sq; }
    __syncthreads();
    if (wid == 0) {
        float ss = (lid < 8) ? red_s[lid] : 0.f;
        float qq = (lid < 8) ? red_q[lid] : 0.f;
        for (int o = 4; o > 0; o >>= 1) {
            ss += __shfl_xor_sync(0xffffffffu, ss, o);
            qq += __shfl_xor_sync(0xffffffffu, qq, o);
        }
        if (lid == 0) { red_s[0] = ss; red_q[0] = qq; }
    }
    __syncthreads();
    float mean = red_s[0] * (1.0f / DMODEL);
    float var  = red_q[0] * (1.0f / DMODEL) - mean * mean;
    float rstd = rsqrtf(var + 1e-5f);

    float4 gv = reinterpret_cast<const float4*>(g)[t];
    float4 bv = reinterpret_cast<const float4*>(b)[t];
    float o0 = (v.x - mean) * rstd * gv.x + bv.x;
    float o1 = (v.y - mean) * rstd * gv.y + bv.y;
    float o2 = (v.z - mean) * rstd * gv.z + bv.z;
    float o3 = (v.w - mean) * rstd * gv.w + bv.w;
    __nv_bfloat16 h0,l0,h1,l1,h2,l2,h3,l3;
    split_bf16(o0,h0,l0); split_bf16(o1,h1,l1); split_bf16(o2,h2,l2); split_bf16(o3,h3,l3);
    __nv_bfloat162* ph = reinterpret_cast<__nv_bfloat162*>(ohi + (size_t)row * DMODEL);
    __nv_bfloat162* pl = reinterpret_cast<__nv_bfloat162*>(olo + (size_t)row * DMODEL);
    ph[t*2]   = __nv_bfloat162(h0, h1);
    ph[t*2+1] = __nv_bfloat162(h2, h3);
    pl[t*2]   = __nv_bfloat162(l0, l1);
    pl[t*2+1] = __nv_bfloat162(l2, l3);
}

// ---------------- mma.sync bf16x2-split GEMM ----------------
// C[M,N] = (Ahi+Alo)[M,K] @ (Bhi+Blo)[N,K]^T
// CTA tile 128x128, KBLK=64, 8 warps (2 M x 4 N), warp tile 64x32.
// EPI: 0 = fp32 C; 1 = +bias +resid -> fp32 C; 2 = +bias, GELU -> bf16 hi/lo
#define KBLK 64
#define STAGE_BYTES 65536            // 4 tensors x 128 rows x 128B
#define MG_SMEM (2 * STAGE_BYTES)    // 131072

template<int EPI>
__global__ __launch_bounds__(256, 1)
void mma_gemm(const __nv_bfloat16* __restrict__ Ahi, const __nv_bfloat16* __restrict__ Alo,
              const __nv_bfloat16* __restrict__ Bhi, const __nv_bfloat16* __restrict__ Blo,
              const float* __restrict__ bias, const float* __restrict__ resid,
              float* __restrict__ C, __nv_bfloat16* __restrict__ Chi,
              __nv_bfloat16* __restrict__ Clo, int M, int N, int K)
{
    extern __shared__ char sm[];
    uint32_t sb = smem_u32(sm);

    int tid  = threadIdx.x;
    int wid  = tid >> 5;
    int lane = tid & 31;
    int wm   = wid & 1;          // 0..1 (M)
    int wn   = wid >> 1;         // 0..3 (N)

    int row0 = blockIdx.y * 128, col0 = blockIdx.x * 128;
    const __nv_bfloat16* pAhi = Ahi + (size_t)row0 * K;
    const __nv_bfloat16* pAlo = Alo + (size_t)row0 * K;
    const __nv_bfloat16* pBhi = Bhi + (size_t)col0 * K;
    const __nv_bfloat16* pBlo = Blo + (size_t)col0 * K;

    int KB = K / KBLK;

    // cp.async mapping: per tensor, 128 rows x 8 chunks of 16B; 4 chunks/thread
    int ld_r[4], ld_c[4];
    uint32_t ld_so[4];
    #pragma unroll
    for (int i = 0; i < 4; i++) {
        int idx = tid + (i << 8);
        ld_r[i] = idx >> 3;
        ld_c[i] = idx & 7;
        ld_so[i] = SMEM_SWZ128((uint32_t)(ld_r[i] * 128 + ld_c[i] * 16));
    }

    auto load_stage = [&](int kb) {
        uint32_t base = sb + (kb & 1) * STAGE_BYTES;
        int koff = kb * KBLK;
        #pragma unroll
        for (int i = 0; i < 4; i++) {
            size_t go = (size_t)ld_r[i] * K + koff + ld_c[i] * 8;
            CP_ASYNC16(base + ld_so[i],         (const void*)(pAhi + go));
            CP_ASYNC16(base + 16384 + ld_so[i], (const void*)(pAlo + go));
            CP_ASYNC16(base + 32768 + ld_so[i], (const void*)(pBhi + go));
            CP_ASYNC16(base + 49152 + ld_so[i], (const void*)(pBlo + go));
        }
        CP_COMMIT();
    };

    float acc[4][4][4];
    #pragma unroll
    for (int i = 0; i < 4; i++)
        #pragma unroll
        for (int j = 0; j < 4; j++)
            #pragma unroll
            for (int e = 0; e < 4; e++) acc[i][j][e] = 0.f;

    load_stage(0);

    for (int kb = 0; kb < KB; kb++) {
        if (kb + 1 < KB) { load_stage(kb + 1); CP_WAIT(1); }
        else             { CP_WAIT(0); }
        __syncthreads();

        uint32_t base = sb + (kb & 1) * STAGE_BYTES;
        uint32_t sAh = base, sAl = base + 16384, sBh = base + 32768, sBl = base + 49152;

        #pragma unroll
        for (int kk = 0; kk < 4; kk++) {
            uint32_t ah[4][4], al[4][4], bh[4][2], bl[4][2];
            // A fragments: 4 m16 tiles
            int acol2 = (kk * 16 + ((lane >> 4) << 3)) * 2;
            #pragma unroll
            for (int mt = 0; mt < 4; mt++) {
                int row = wm * 64 + mt * 16 + (lane & 15);
                uint32_t off = SMEM_SWZ128((uint32_t)(row * 128 + acol2));
                ldsm_x4(ah[mt], sAh + off);
                ldsm_x4(al[mt], sAl + off);
            }
            // B fragments: 4 n8 tiles via 2 x4 loads per precision
            int bcol2 = (kk * 16 + (((lane >> 3) & 1) << 3)) * 2;
            int brow  = wn * 32 + ((lane >> 4) << 3) + (lane & 7);
            #pragma unroll
            for (int p = 0; p < 2; p++) {
                uint32_t off = SMEM_SWZ128((uint32_t)((brow + p * 16) * 128 + bcol2));
                uint32_t t[4];
                ldsm_x4(t, sBh + off);
                bh[p*2][0] = t[0]; bh[p*2][1] = t[1]; bh[p*2+1][0] = t[2]; bh[p*2+1][1] = t[3];
                ldsm_x4(t, sBl + off);
                bl[p*2][0] = t[0]; bl[p*2][1] = t[1]; bl[p*2+1][0] = t[2]; bl[p*2+1][1] = t[3];
            }
            #pragma unroll
            for (int mt = 0; mt < 4; mt++)
                #pragma unroll
                for (int nt = 0; nt < 4; nt++) {
                    mma16816(acc[mt][nt], ah[mt], bh[nt]);
                    mma16816(acc[mt][nt], ah[mt], bl[nt]);
                    mma16816(acc[mt][nt], al[mt], bh[nt]);
                }
        }
        __syncthreads();
    }

    // epilogue
    int g  = lane >> 2;
    int c2 = (lane & 3) * 2;
    #pragma unroll
    for (int mt = 0; mt < 4; mt++) {
        #pragma unroll
        for (int nt = 0; nt < 4; nt++) {
            int row = row0 + wm * 64 + mt * 16 + g;
            int col = col0 + wn * 32 + nt * 8 + c2;
            float d[4] = {acc[mt][nt][0], acc[mt][nt][1], acc[mt][nt][2], acc[mt][nt][3]};
            if (EPI >= 1) {
                float b0 = __ldg(&bias[col]), b1 = __ldg(&bias[col + 1]);
                d[0] += b0; d[1] += b1; d[2] += b0; d[3] += b1;
            }
            if (EPI == 1) {
                float2 r0 = *reinterpret_cast<const float2*>(&resid[(size_t)row * N + col]);
                float2 r1 = *reinterpret_cast<const float2*>(&resid[(size_t)(row + 8) * N + col]);
                d[0] += r0.x; d[1] += r0.y; d[2] += r1.x; d[3] += r1.y;
            }
            if (EPI <= 1) {
                *reinterpret_cast<float2*>(&C[(size_t)row * N + col])       = make_float2(d[0], d[1]);
                *reinterpret_cast<float2*>(&C[(size_t)(row + 8) * N + col]) = make_float2(d[2], d[3]);
            } else {
                float g0 = gelu_exact(d[0]), g1 = gelu_exact(d[1]);
                float g2 = gelu_exact(d[2]), g3 = gelu_exact(d[3]);
                __nv_bfloat16 h0,l0,h1,l1,h2,l2,h3,l3;
                split_bf16(g0,h0,l0); split_bf16(g1,h1,l1);
                split_bf16(g2,h2,l2); split_bf16(g3,h3,l3);
                *reinterpret_cast<__nv_bfloat162*>(&Chi[(size_t)row * N + col])       = __nv_bfloat162(h0, h1);
                *reinterpret_cast<__nv_bfloat162*>(&Clo[(size_t)row * N + col])       = __nv_bfloat162(l0, l1);
                *reinterpret_cast<__nv_bfloat162*>(&Chi[(size_t)(row + 8) * N + col]) = __nv_bfloat162(h2, h3);
                *reinterpret_cast<__nv_bfloat162*>(&Clo[(size_t)(row + 8) * N + col]) = __nv_bfloat162(l2, l3);
            }
        }
    }
}

// ---------------- causal flash attention (fp32, bf16-split output) ----------------
#define AT_PAD 68
#define ATT_SMEM (4 * 64 * AT_PAD * (int)sizeof(float))

__global__ void attn_kernel(const float* __restrict__ Q,
                            const float* __restrict__ K,
                            const float* __restrict__ V,
                            __nv_bfloat16* __restrict__ Ohi,
                            __nv_bfloat16* __restrict__ Olo)
{
    extern __shared__ float smf[];
    float* Qs = smf;
    float* Ks = Qs + 64 * AT_PAD;
    float* Vs = Ks + 64 * AT_PAD;
    float* Ss = Vs + 64 * AT_PAD;

    int tid = threadIdx.x;
    int bh = blockIdx.y;
    int b = bh >> 4, h = bh & 15;
    int qt = blockIdx.x;

    const float* qbase = Q + ((size_t)(b * SEQ + qt * 64)) * DMODEL + h * DK;
    for (int i = tid; i < 64 * 16; i += 256) {
        int row = i >> 4, c4 = (i & 15) * 4;
        float4 v = *reinterpret_cast<const float4*>(qbase + (size_t)row * DMODEL + c4);
        float* d = &Qs[row * AT_PAD + c4];
        d[0] = v.x; d[1] = v.y; d[2] = v.z; d[3] = v.w;
    }

    int r  = tid >> 2;
    int cg = tid & 3;
    int q_global = qt * 64 + r;

    float acc[16];
    #pragma unroll
    for (int i = 0; i < 16; i++) acc[i] = 0.f;
    float m_old = -INFINITY, l = 0.f;

    for (int kt = 0; kt <= qt; kt++) {
        __syncthreads();
        const float* kbase = K + ((size_t)(b * SEQ + kt * 64)) * DMODEL + h * DK;
        const float* vbase = V + ((size_t)(b * SEQ + kt * 64)) * DMODEL + h * DK;
        for (int i = tid; i < 64 * 16; i += 256) {
            int row = i >> 4, c4 = (i & 15) * 4;
            float4 vk = *reinterpret_cast<const float4*>(kbase + (size_t)row * DMODEL + c4);
            float* dk = &Ks[row * AT_PAD + c4];
            dk[0] = vk.x; dk[1] = vk.y; dk[2] = vk.z; dk[3] = vk.w;
            float4 vv = *reinterpret_cast<const float4*>(vbase + (size_t)row * DMODEL + c4);
            float* dv = &Vs[row * AT_PAD + c4];
            dv[0] = vv.x; dv[1] = vv.y; dv[2] = vv.z; dv[3] = vv.w;
        }
        __syncthreads();

        float s[16];
        const float* qr = &Qs[r * AT_PAD];
        #pragma unroll
        for (int jj = 0; jj < 16; jj++) {
            int j = cg * 16 + jj;
            const float* kr = &Ks[j * AT_PAD];
            float a = 0.f;
            #pragma unroll
            for (int d = 0; d < 64; d++) a += qr[d] * kr[d];
            int k_global = kt * 64 + j;
            s[jj] = (k_global <= q_global) ? a * 0.125f : -INFINITY;
        }

        float tm = s[0];
        #pragma unroll
        for (int jj = 1; jj < 16; jj++) tm = fmaxf(tm, s[jj]);
        tm = fmaxf(tm, __shfl_xor_sync(0xffffffffu, tm, 1));
        tm = fmaxf(tm, __shfl_xor_sync(0xffffffffu, tm, 2));

        float m_new = fmaxf(m_old, tm);
        float alpha = __expf(m_old - m_new);

        float psum = 0.f;
        #pragma unroll
        for (int jj = 0; jj < 16; jj++) {
            float p = __expf(s[jj] - m_new);
            Ss[r * AT_PAD + cg * 16 + jj] = p;
            psum += p;
        }
        psum += __shfl_xor_sync(0xffffffffu, psum, 1);
        psum += __shfl_xor_sync(0xffffffffu, psum, 2);

        l = l * alpha + psum;
        m_old = m_new;
        #pragma unroll
        for (int i = 0; i < 16; i++) acc[i] *= alpha;

        __syncthreads();

        for (int j = 0; j < 64; j++) {
            float p = Ss[r * AT_PAD + j];
            const float* vr = &Vs[j * AT_PAD + cg * 16];
            #pragma unroll
            for (int c = 0; c < 16; c++) acc[c] += p * vr[c];
        }
    }

    float inv = 1.0f / l;
    size_t obase = ((size_t)(b * SEQ + q_global)) * DMODEL + h * DK + cg * 16;
    __nv_bfloat162* ph = reinterpret_cast<__nv_bfloat162*>(Ohi + obase);
    __nv_bfloat162* pl = reinterpret_cast<__nv_bfloat162*>(Olo + obase);
    #pragma unroll
    for (int c = 0; c < 16; c += 2) {
        float o0 = acc[c] * inv, o1 = acc[c+1] * inv;
        __nv_bfloat16 h0,l0,h1,l1;
        split_bf16(o0,h0,l0); split_bf16(o1,h1,l1);
        ph[c >> 1] = __nv_bfloat162(h0, h1);
        pl[c >> 1] = __nv_bfloat162(l0, l1);
    }
}

// ---------------- launch ----------------
extern "C" void kernel_launch(void* const* d_in, const int* in_sizes, int n_in,
                              void* d_out, int out_size)
{
    const float* x     = (const float*)d_in[0];
    const float* ln1_g = (const float*)d_in[1];
    const float* ln1_b = (const float*)d_in[2];
    const float* w_q   = (const float*)d_in[3];
    const float* w_k   = (const float*)d_in[4];
    const float* w_v   = (const float*)d_in[5];
    const float* w_o   = (const float*)d_in[6];
    const float* b_o   = (const float*)d_in[7];
    const float* ln2_g = (const float*)d_in[8];
    const float* ln2_b = (const float*)d_in[9];
    const float* w1    = (const float*)d_in[10];
    const float* b1    = (const float*)d_in[11];
    const float* w2    = (const float*)d_in[12];
    const float* b2    = (const float*)d_in[13];
    float* out = (float*)d_out;

    __nv_bfloat16 *hhi,*hlo,*atthi,*attlo,*ffnhi,*ffnlo;
    __nv_bfloat16 *wq_hi,*wq_lo,*wk_hi,*wk_lo,*wv_hi,*wv_lo,*wo_hi,*wo_lo,*w1_hi,*w1_lo,*w2_hi,*w2_lo;
    float *q,*k,*v,*x1;
    cudaGetSymbolAddress((void**)&hhi,   g_hhi);   cudaGetSymbolAddress((void**)&hlo,   g_hlo);
    cudaGetSymbolAddress((void**)&q,     g_q);     cudaGetSymbolAddress((void**)&k,     g_k);
    cudaGetSymbolAddress((void**)&v,     g_v);
    cudaGetSymbolAddress((void**)&atthi, g_atthi); cudaGetSymbolAddress((void**)&attlo, g_attlo);
    cudaGetSymbolAddress((void**)&x1,    g_x1);
    cudaGetSymbolAddress((void**)&ffnhi, g_ffnhi); cudaGetSymbolAddress((void**)&ffnlo, g_ffnlo);
    cudaGetSymbolAddress((void**)&wq_hi, g_wqT_hi); cudaGetSymbolAddress((void**)&wq_lo, g_wqT_lo);
    cudaGetSymbolAddress((void**)&wk_hi, g_wkT_hi); cudaGetSymbolAddress((void**)&wk_lo, g_wkT_lo);
    cudaGetSymbolAddress((void**)&wv_hi, g_wvT_hi); cudaGetSymbolAddress((void**)&wv_lo, g_wvT_lo);
    cudaGetSymbolAddress((void**)&wo_hi, g_woT_hi); cudaGetSymbolAddress((void**)&wo_lo, g_woT_lo);
    cudaGetSymbolAddress((void**)&w1_hi, g_w1T_hi); cudaGetSymbolAddress((void**)&w1_lo, g_w1T_lo);
    cudaGetSymbolAddress((void**)&w2_hi, g_w2T_hi); cudaGetSymbolAddress((void**)&w2_lo, g_w2T_lo);

    cudaFuncSetAttribute(attn_kernel, cudaFuncAttributeMaxDynamicSharedMemorySize, ATT_SMEM);
    cudaFuncSetAttribute(mma_gemm<0>, cudaFuncAttributeMaxDynamicSharedMemorySize, MG_SMEM);
    cudaFuncSetAttribute(mma_gemm<1>, cudaFuncAttributeMaxDynamicSharedMemorySize, MG_SMEM);
    cudaFuncSetAttribute(mma_gemm<2>, cudaFuncAttributeMaxDynamicSharedMemorySize, MG_SMEM);

    dim3 tb(32, 8);
    wsplitT<<<dim3(DMODEL/32, DMODEL/32), tb>>>(w_q, wq_hi, wq_lo, DMODEL, DMODEL);
    wsplitT<<<dim3(DMODEL/32, DMODEL/32), tb>>>(w_k, wk_hi, wk_lo, DMODEL, DMODEL);
    wsplitT<<<dim3(DMODEL/32, DMODEL/32), tb>>>(w_v, wv_hi, wv_lo, DMODEL, DMODEL);
    wsplitT<<<dim3(DMODEL/32, DMODEL/32), tb>>>(w_o, wo_hi, wo_lo, DMODEL, DMODEL);
    wsplitT<<<dim3(FFN_DIM/32, DMODEL/32), tb>>>(w1, w1_hi, w1_lo, DMODEL, FFN_DIM);
    wsplitT<<<dim3(DMODEL/32, FFN_DIM/32), tb>>>(w2, w2_hi, w2_lo, FFN_DIM, DMODEL);

    dim3 gP(DMODEL / 128, ROWS / 128);    // (8, 64)
    dim3 gF1(FFN_DIM / 128, ROWS / 128);  // (32, 64)

    // 1) LN1 -> bf16 split
    ln_kernel<<<ROWS, 256>>>(x, ln1_g, ln1_b, hhi, hlo);
    // 2) QKV projections
    mma_gemm<0><<<gP, 256, MG_SMEM>>>(hhi, hlo, wq_hi, wq_lo, nullptr, nullptr, q, nullptr, nullptr, ROWS, DMODEL, DMODEL);
    mma_gemm<0><<<gP, 256, MG_SMEM>>>(hhi, hlo, wk_hi, wk_lo, nullptr, nullptr, k, nullptr, nullptr, ROWS, DMODEL, DMODEL);
    mma_gemm<0><<<gP, 256, MG_SMEM>>>(hhi, hlo, wv_hi, wv_lo, nullptr, nullptr, v, nullptr, nullptr, ROWS, DMODEL, DMODEL);
    // 3) causal attention -> bf16 split
    attn_kernel<<<dim3(SEQ / 64, BATCH * NHEAD), 256, ATT_SMEM>>>(q, k, v, atthi, attlo);
    // 4) O projection + bias + residual -> x1 (fp32)
    mma_gemm<1><<<gP, 256, MG_SMEM>>>(atthi, attlo, wo_hi, wo_lo, b_o, x, x1, nullptr, nullptr, ROWS, DMODEL, DMODEL);
    // 5) LN2 -> bf16 split
    ln_kernel<<<ROWS, 256>>>(x1, ln2_g, ln2_b, hhi, hlo);
    // 6) FFN up + GELU -> bf16 split
    mma_gemm<2><<<gF1, 256, MG_SMEM>>>(hhi, hlo, w1_hi, w1_lo, b1, nullptr, nullptr, ffnhi, ffnlo, ROWS, FFN_DIM, DMODEL);
    // 7) FFN down + bias + residual -> out
    mma_gemm<1><<<gP, 256, MG_SMEM>>>(ffnhi, ffnlo, w2_hi, w2_lo, b2, x1, out, nullptr, nullptr, ROWS, DMODEL, FFN_DIM);
}

// round 4
// speedup vs baseline: 3.6244x; 1.8962x over previous
#include <cuda_runtime.h>
#include <cuda_bf16.h>
#include <math.h>
#include <stdint.h>

#define BATCH   16
#define SEQ     512
#define DMODEL  1024
#define NHEAD   16
#define DK      64
#define FFN_DIM 4096
#define ROWS    (BATCH * SEQ)        // 8192
#define QKV_N   (3 * DMODEL)         // 3072

// ---------------- scratch (device globals; no allocation) ----------------
__device__ __nv_bfloat16 g_hhi [ROWS * DMODEL];
__device__ __nv_bfloat16 g_hlo [ROWS * DMODEL];
__device__ __nv_bfloat16 g_qkvhi[ROWS * QKV_N];
__device__ __nv_bfloat16 g_qkvlo[ROWS * QKV_N];
__device__ __nv_bfloat16 g_atthi[ROWS * DMODEL];
__device__ __nv_bfloat16 g_attlo[ROWS * DMODEL];
__device__ float g_x1 [ROWS * DMODEL];
__device__ __nv_bfloat16 g_ffnhi[ROWS * FFN_DIM];
__device__ __nv_bfloat16 g_ffnlo[ROWS * FFN_DIM];
// transposed + split weights: T[N,K]
__device__ __nv_bfloat16 g_wqkvT_hi[QKV_N*DMODEL], g_wqkvT_lo[QKV_N*DMODEL];
__device__ __nv_bfloat16 g_woT_hi[DMODEL*DMODEL],  g_woT_lo[DMODEL*DMODEL];
__device__ __nv_bfloat16 g_w1T_hi[DMODEL*FFN_DIM], g_w1T_lo[DMODEL*FFN_DIM];
__device__ __nv_bfloat16 g_w2T_hi[FFN_DIM*DMODEL], g_w2T_lo[FFN_DIM*DMODEL];

// ---------------- helpers ----------------
__device__ __forceinline__ uint32_t smem_u32(const void* p) {
    uint32_t a;
    asm("{ .reg .u64 t; cvta.to.shared.u64 t, %1; cvt.u32.u64 %0, t; }" : "=r"(a) : "l"(p));
    return a;
}
#define CP_ASYNC16(dst, src) \
    asm volatile("cp.async.cg.shared.global [%0], [%1], 16;" :: "r"(dst), "l"(src) : "memory")
#define CP_COMMIT() asm volatile("cp.async.commit_group;" ::: "memory")
#define CP_WAIT(n)  asm volatile("cp.async.wait_group %0;" :: "n"(n) : "memory")
#define SMEM_SWZ128(off) ((off) ^ (((off) >> 3) & 0x70))

__device__ __forceinline__ void ldsm_x4(uint32_t* r, uint32_t addr) {
    asm volatile("ldmatrix.sync.aligned.m8n8.x4.shared.b16 {%0,%1,%2,%3}, [%4];"
        : "=r"(r[0]), "=r"(r[1]), "=r"(r[2]), "=r"(r[3]) : "r"(addr));
}
__device__ __forceinline__ void ldsm_x4_t(uint32_t* r, uint32_t addr) {
    asm volatile("ldmatrix.sync.aligned.m8n8.x4.trans.shared.b16 {%0,%1,%2,%3}, [%4];"
        : "=r"(r[0]), "=r"(r[1]), "=r"(r[2]), "=r"(r[3]) : "r"(addr));
}
__device__ __forceinline__ void mma16816(float* d, const uint32_t* a, const uint32_t* b) {
    asm volatile("mma.sync.aligned.m16n8k16.row.col.f32.bf16.bf16.f32 "
        "{%0,%1,%2,%3}, {%4,%5,%6,%7}, {%8,%9}, {%0,%1,%2,%3};"
        : "+f"(d[0]), "+f"(d[1]), "+f"(d[2]), "+f"(d[3])
        : "r"(a[0]), "r"(a[1]), "r"(a[2]), "r"(a[3]), "r"(b[0]), "r"(b[1]));
}

__device__ __forceinline__ float gelu_exact(float v) {
    return 0.5f * v * (1.0f + erff(v * 0.70710678118654752f));
}
__device__ __forceinline__ void split_bf16(float v, __nv_bfloat16& hi, __nv_bfloat16& lo) {
    hi = __float2bfloat16(v);
    lo = __float2bfloat16(v - __bfloat162float(hi));
}
__device__ __forceinline__ uint32_t pack2(__nv_bfloat16 a, __nv_bfloat16 b) {
    __nv_bfloat162 t(a, b);
    return *reinterpret_cast<uint32_t*>(&t);
}

// ---------------- weight transpose + split: W[K,N] -> T[N,K] hi/lo ----------------
__global__ void wsplitT(const float* __restrict__ W,
                        __nv_bfloat16* __restrict__ Thi,
                        __nv_bfloat16* __restrict__ Tlo, int K, int N)
{
    __shared__ float t[32][33];
    int n0 = blockIdx.x * 32, k0 = blockIdx.y * 32;
    int tx = threadIdx.x, ty = threadIdx.y;
    #pragma unroll
    for (int i = 0; i < 4; i++)
        t[ty + 8*i][tx] = W[(size_t)(k0 + ty + 8*i) * N + n0 + tx];
    __syncthreads();
    #pragma unroll
    for (int i = 0; i < 4; i++) {
        float v = t[tx][ty + 8*i];
        __nv_bfloat16 hi, lo; split_bf16(v, hi, lo);
        size_t o = (size_t)(n0 + ty + 8*i) * K + k0 + tx;
        Thi[o] = hi; Tlo[o] = lo;
    }
}

// ---------------- LayerNorm: one block per row, outputs bf16 hi/lo ----------------
__global__ void ln_kernel(const float* __restrict__ x,
                          const float* __restrict__ g,
                          const float* __restrict__ b,
                          __nv_bfloat16* __restrict__ ohi,
                          __nv_bfloat16* __restrict__ olo)
{
    int row = blockIdx.x;
    const float4* xr = reinterpret_cast<const float4*>(x + (size_t)row * DMODEL);
    int t = threadIdx.x;
    float4 v = xr[t];
    float s  = v.x + v.y + v.z + v.w;
    float sq = v.x*v.x + v.y*v.y + v.z*v.z + v.w*v.w;

    __shared__ float red_s[8], red_q[8];
    for (int o = 16; o > 0; o >>= 1) {
        s  += __shfl_xor_sync(0xffffffffu, s,  o);
        sq += __shfl_xor_sync(0xffffffffu, sq, o);
    }
    int wid = t >> 5, lid = t & 31;
    if (lid == 0) { red_s[wid] = s; red_q[wid] = sq; }
    __syncthreads();
    if (wid == 0) {
        float ss = (lid < 8) ? red_s[lid] : 0.f;
        float qq = (lid < 8) ? red_q[lid] : 0.f;
        for (int o = 4; o > 0; o >>= 1) {
            ss += __shfl_xor_sync(0xffffffffu, ss, o);
            qq += __shfl_xor_sync(0xffffffffu, qq, o);
        }
        if (lid == 0) { red_s[0] = ss; red_q[0] = qq; }
    }
    __syncthreads();
    float mean = red_s[0] * (1.0f / DMODEL);
    float var  = red_q[0] * (1.0f / DMODEL) - mean * mean;
    float rstd = rsqrtf(var + 1e-5f);

    float4 gv = reinterpret_cast<const float4*>(g)[t];
    float4 bv = reinterpret_cast<const float4*>(b)[t];
    float o0 = (v.x - mean) * rstd * gv.x + bv.x;
    float o1 = (v.y - mean) * rstd * gv.y + bv.y;
    float o2 = (v.z - mean) * rstd * gv.z + bv.z;
    float o3 = (v.w - mean) * rstd * gv.w + bv.w;
    __nv_bfloat16 h0,l0,h1,l1,h2,l2,h3,l3;
    split_bf16(o0,h0,l0); split_bf16(o1,h1,l1); split_bf16(o2,h2,l2); split_bf16(o3,h3,l3);
    __nv_bfloat162* ph = reinterpret_cast<__nv_bfloat162*>(ohi + (size_t)row * DMODEL);
    __nv_bfloat162* pl = reinterpret_cast<__nv_bfloat162*>(olo + (size_t)row * DMODEL);
    ph[t*2]   = __nv_bfloat162(h0, h1);
    ph[t*2+1] = __nv_bfloat162(h2, h3);
    pl[t*2]   = __nv_bfloat162(l0, l1);
    pl[t*2+1] = __nv_bfloat162(l2, l3);
}

// ---------------- mma.sync bf16x2-split GEMM (3-stage pipeline) ----------------
// C[M,N] = (Ahi+Alo)[M,K] @ (Bhi+Blo)[N,K]^T
// CTA tile 128x128, KBLK=64, 8 warps (2 M x 4 N), warp tile 64x32.
// EPI: 0 = bf16 hi/lo split C; 1 = +bias +resid -> fp32 C; 2 = +bias, GELU -> bf16 hi/lo
#define KBLK 64
#define STAGE_BYTES 65536            // 4 tensors x 128 rows x 128B
#define MG_SMEM (3 * STAGE_BYTES)    // 196608

template<int EPI>
__global__ __launch_bounds__(256, 1)
void mma_gemm(const __nv_bfloat16* __restrict__ Ahi, const __nv_bfloat16* __restrict__ Alo,
              const __nv_bfloat16* __restrict__ Bhi, const __nv_bfloat16* __restrict__ Blo,
              const float* __restrict__ bias, const float* __restrict__ resid,
              float* __restrict__ C, __nv_bfloat16* __restrict__ Chi,
              __nv_bfloat16* __restrict__ Clo, int M, int N, int K)
{
    extern __shared__ char sm[];
    uint32_t sb = smem_u32(sm);

    int tid  = threadIdx.x;
    int wid  = tid >> 5;
    int lane = tid & 31;
    int wm   = wid & 1;
    int wn   = wid >> 1;

    int row0 = blockIdx.y * 128, col0 = blockIdx.x * 128;
    const __nv_bfloat16* pAhi = Ahi + (size_t)row0 * K;
    const __nv_bfloat16* pAlo = Alo + (size_t)row0 * K;
    const __nv_bfloat16* pBhi = Bhi + (size_t)col0 * K;
    const __nv_bfloat16* pBlo = Blo + (size_t)col0 * K;

    int KB = K / KBLK;

    int ld_r[4], ld_c[4];
    uint32_t ld_so[4];
    #pragma unroll
    for (int i = 0; i < 4; i++) {
        int idx = tid + (i << 8);
        ld_r[i] = idx >> 3;
        ld_c[i] = idx & 7;
        ld_so[i] = SMEM_SWZ128((uint32_t)(ld_r[i] * 128 + ld_c[i] * 16));
    }

    auto load_stage = [&](int kb) {
        uint32_t base = sb + (kb % 3) * STAGE_BYTES;
        int koff = kb * KBLK;
        #pragma unroll
        for (int i = 0; i < 4; i++) {
            size_t go = (size_t)ld_r[i] * K + koff + ld_c[i] * 8;
            CP_ASYNC16(base + ld_so[i],         (const void*)(pAhi + go));
            CP_ASYNC16(base + 16384 + ld_so[i], (const void*)(pAlo + go));
            CP_ASYNC16(base + 32768 + ld_so[i], (const void*)(pBhi + go));
            CP_ASYNC16(base + 49152 + ld_so[i], (const void*)(pBlo + go));
        }
        CP_COMMIT();
    };

    float acc[4][4][4];
    #pragma unroll
    for (int i = 0; i < 4; i++)
        #pragma unroll
        for (int j = 0; j < 4; j++)
            #pragma unroll
            for (int e = 0; e < 4; e++) acc[i][j][e] = 0.f;

    load_stage(0);
    load_stage(1);

    for (int kb = 0; kb < KB; kb++) {
        if (kb + 2 < KB) load_stage(kb + 2);
        else             CP_COMMIT();
        CP_WAIT(2);
        __syncthreads();

        uint32_t base = sb + (kb % 3) * STAGE_BYTES;
        uint32_t sAh = base, sAl = base + 16384, sBh = base + 32768, sBl = base + 49152;

        #pragma unroll
        for (int kk = 0; kk < 4; kk++) {
            uint32_t ah[4][4], al[4][4], bh[4][2], bl[4][2];
            int acol2 = (kk * 16 + ((lane >> 4) << 3)) * 2;
            #pragma unroll
            for (int mt = 0; mt < 4; mt++) {
                int row = wm * 64 + mt * 16 + (lane & 15);
                uint32_t off = SMEM_SWZ128((uint32_t)(row * 128 + acol2));
                ldsm_x4(ah[mt], sAh + off);
                ldsm_x4(al[mt], sAl + off);
            }
            int bcol2 = (kk * 16 + (((lane >> 3) & 1) << 3)) * 2;
            int brow  = wn * 32 + ((lane >> 4) << 3) + (lane & 7);
            #pragma unroll
            for (int p = 0; p < 2; p++) {
                uint32_t off = SMEM_SWZ128((uint32_t)((brow + p * 16) * 128 + bcol2));
                uint32_t t[4];
                ldsm_x4(t, sBh + off);
                bh[p*2][0] = t[0]; bh[p*2][1] = t[1]; bh[p*2+1][0] = t[2]; bh[p*2+1][1] = t[3];
                ldsm_x4(t, sBl + off);
                bl[p*2][0] = t[0]; bl[p*2][1] = t[1]; bl[p*2+1][0] = t[2]; bl[p*2+1][1] = t[3];
            }
            #pragma unroll
            for (int mt = 0; mt < 4; mt++)
                #pragma unroll
                for (int nt = 0; nt < 4; nt++) {
                    mma16816(acc[mt][nt], ah[mt], bh[nt]);
                    mma16816(acc[mt][nt], ah[mt], bl[nt]);
                    mma16816(acc[mt][nt], al[mt], bh[nt]);
                }
        }
        __syncthreads();
    }

    // epilogue
    int g  = lane >> 2;
    int c2 = (lane & 3) * 2;
    #pragma unroll
    for (int mt = 0; mt < 4; mt++) {
        #pragma unroll
        for (int nt = 0; nt < 4; nt++) {
            int row = row0 + wm * 64 + mt * 16 + g;
            int col = col0 + wn * 32 + nt * 8 + c2;
            float d[4] = {acc[mt][nt][0], acc[mt][nt][1], acc[mt][nt][2], acc[mt][nt][3]};
            if (EPI >= 1) {
                float b0 = __ldg(&bias[col]), b1 = __ldg(&bias[col + 1]);
                d[0] += b0; d[1] += b1; d[2] += b0; d[3] += b1;
            }
            if (EPI == 1) {
                float2 r0 = *reinterpret_cast<const float2*>(&resid[(size_t)row * N + col]);
                float2 r1 = *reinterpret_cast<const float2*>(&resid[(size_t)(row + 8) * N + col]);
                d[0] += r0.x; d[1] += r0.y; d[2] += r1.x; d[3] += r1.y;
                *reinterpret_cast<float2*>(&C[(size_t)row * N + col])       = make_float2(d[0], d[1]);
                *reinterpret_cast<float2*>(&C[(size_t)(row + 8) * N + col]) = make_float2(d[2], d[3]);
            } else {
                if (EPI == 2) {
                    d[0] = gelu_exact(d[0]); d[1] = gelu_exact(d[1]);
                    d[2] = gelu_exact(d[2]); d[3] = gelu_exact(d[3]);
                }
                __nv_bfloat16 h0,l0,h1,l1,h2,l2,h3,l3;
                split_bf16(d[0],h0,l0); split_bf16(d[1],h1,l1);
                split_bf16(d[2],h2,l2); split_bf16(d[3],h3,l3);
                *reinterpret_cast<__nv_bfloat162*>(&Chi[(size_t)row * N + col])       = __nv_bfloat162(h0, h1);
                *reinterpret_cast<__nv_bfloat162*>(&Clo[(size_t)row * N + col])       = __nv_bfloat162(l0, l1);
                *reinterpret_cast<__nv_bfloat162*>(&Chi[(size_t)(row + 8) * N + col]) = __nv_bfloat162(h2, h3);
                *reinterpret_cast<__nv_bfloat162*>(&Clo[(size_t)(row + 8) * N + col]) = __nv_bfloat162(l2, l3);
            }
        }
    }
}

// ---------------- tensor-core causal flash attention ----------------
// CTA: 128 threads (4 warps), one (b, h, qtile64). Warp w owns q rows [16w, 16w+16).
// Q/K/V are bf16 hi/lo slices of the fused QKV buffer (row stride 3072).
// smem: sQhi(8K) sQlo(8K) | stage s: Khi Klo Vhi Vlo (8K each), 2 stages.
#define ATT_SMEM (16384 + 2 * 32768)   // 81920

__global__ __launch_bounds__(128, 2)
void attn_mma(const __nv_bfloat16* __restrict__ QKVhi,
              const __nv_bfloat16* __restrict__ QKVlo,
              __nv_bfloat16* __restrict__ Ohi,
              __nv_bfloat16* __restrict__ Olo)
{
    extern __shared__ char sm[];
    uint32_t sb = smem_u32(sm);
    int tid = threadIdx.x, lane = tid & 31, w = tid >> 5;
    int bh = blockIdx.y, b = bh >> 4, h = bh & 15;
    int qt = blockIdx.x;
    const int QS = QKV_N;   // 3072

    // ---- issue Q loads ----
    {
        size_t q0 = (size_t)(b * SEQ + qt * 64) * QS + h * DK;
        #pragma unroll
        for (int i = 0; i < 4; i++) {
            int idx = tid + (i << 7);
            int r = idx >> 3, c = idx & 7;
            uint32_t so = SMEM_SWZ128((uint32_t)(r * 128 + c * 16));
            size_t go = q0 + (size_t)r * QS + c * 8;
            CP_ASYNC16(sb + so,        (const void*)(QKVhi + go));
            CP_ASYNC16(sb + 8192 + so, (const void*)(QKVlo + go));
        }
    }

    auto load_kv = [&](int kt) {
        uint32_t base = sb + 16384 + (kt & 1) * 32768;
        size_t k0 = (size_t)(b * SEQ + kt * 64) * QS + h * DK + DMODEL;
        size_t v0 = k0 + DMODEL;
        #pragma unroll
        for (int i = 0; i < 4; i++) {
            int idx = tid + (i << 7);
            int r = idx >> 3, c = idx & 7;
            uint32_t so = SMEM_SWZ128((uint32_t)(r * 128 + c * 16));
            size_t gk = k0 + (size_t)r * QS + c * 8;
            size_t gv = v0 + (size_t)r * QS + c * 8;
            CP_ASYNC16(base + so,         (const void*)(QKVhi + gk));
            CP_ASYNC16(base + 8192 + so,  (const void*)(QKVlo + gk));
            CP_ASYNC16(base + 16384 + so, (const void*)(QKVhi + gv));
            CP_ASYNC16(base + 24576 + so, (const void*)(QKVlo + gv));
        }
        CP_COMMIT();
    };

    load_kv(0);      // commits Q + KV0 as one group
    CP_WAIT(0);
    __syncthreads();

    // ---- hoist Q fragments ----
    uint32_t qh[4][4], ql[4][4];
    {
        int arow = w * 16 + (lane & 15);
        #pragma unroll
        for (int s = 0; s < 4; s++) {
            uint32_t off = SMEM_SWZ128((uint32_t)(arow * 128 + (s * 16 + ((lane >> 4) << 3)) * 2));
            ldsm_x4(qh[s], sb + off);
            ldsm_x4(ql[s], sb + 8192 + off);
        }
    }

    float oacc[8][4];
    #pragma unroll
    for (int i = 0; i < 8; i++)
        #pragma unroll
        for (int e = 0; e < 4; e++) oacc[i][e] = 0.f;
    float m0 = -1e30f, m1 = -1e30f, l0 = 0.f, l1 = 0.f;

    int r0g = qt * 64 + w * 16 + (lane >> 2);   // global q row (within seq) for c[0..1]
    int r1g = r0g + 8;

    for (int kt = 0; kt <= qt; kt++) {
        if (kt > 0) { CP_WAIT(0); __syncthreads(); }
        if (kt < qt) load_kv(kt + 1);

        uint32_t kbase = sb + 16384 + (kt & 1) * 32768;
        uint32_t vbase = kbase + 16384;

        // ---- S = (Qhi+Qlo)(Khi+Klo)^T, 3-pass ----
        float sacc[8][4];
        #pragma unroll
        for (int i = 0; i < 8; i++)
            #pragma unroll
            for (int e = 0; e < 4; e++) sacc[i][e] = 0.f;

        int b_r = ((lane >> 4) << 3) + (lane & 7);
        #pragma unroll
        for (int s = 0; s < 4; s++) {
            int b_c2 = (s * 16 + (((lane >> 3) & 1) << 3)) * 2;
            #pragma unroll
            for (int np = 0; np < 4; np++) {
                uint32_t off = SMEM_SWZ128((uint32_t)((np * 16 + b_r) * 128 + b_c2));
                uint32_t th[4], tl[4];
                ldsm_x4(th, kbase + off);
                ldsm_x4(tl, kbase + 8192 + off);
                uint32_t kh0[2] = {th[0], th[1]}, kh1[2] = {th[2], th[3]};
                uint32_t kl0[2] = {tl[0], tl[1]}, kl1[2] = {tl[2], tl[3]};
                mma16816(sacc[2*np],   qh[s], kh0);
                mma16816(sacc[2*np],   qh[s], kl0);
                mma16816(sacc[2*np],   ql[s], kh0);
                mma16816(sacc[2*np+1], qh[s], kh1);
                mma16816(sacc[2*np+1], qh[s], kl1);
                mma16816(sacc[2*np+1], ql[s], kh1);
            }
        }

        // ---- scale + causal mask ----
        #pragma unroll
        for (int nt = 0; nt < 8; nt++)
            #pragma unroll
            for (int e = 0; e < 4; e++) sacc[nt][e] *= 0.125f;
        if (kt == qt) {
            #pragma unroll
            for (int nt = 0; nt < 8; nt++) {
                int colb = kt * 64 + nt * 8 + 2 * (lane & 3);
                #pragma unroll
                for (int e = 0; e < 2; e++) {
                    if (colb + e > r0g) sacc[nt][e]     = -1e30f;
                    if (colb + e > r1g) sacc[nt][2 + e] = -1e30f;
                }
            }
        }

        // ---- online softmax ----
        float mx0 = sacc[0][0], mx1 = sacc[0][2];
        #pragma unroll
        for (int nt = 0; nt < 8; nt++) {
            mx0 = fmaxf(mx0, fmaxf(sacc[nt][0], sacc[nt][1]));
            mx1 = fmaxf(mx1, fmaxf(sacc[nt][2], sacc[nt][3]));
        }
        mx0 = fmaxf(mx0, __shfl_xor_sync(0xffffffffu, mx0, 1));
        mx0 = fmaxf(mx0, __shfl_xor_sync(0xffffffffu, mx0, 2));
        mx1 = fmaxf(mx1, __shfl_xor_sync(0xffffffffu, mx1, 1));
        mx1 = fmaxf(mx1, __shfl_xor_sync(0xffffffffu, mx1, 2));
        float mn0 = fmaxf(m0, mx0), mn1 = fmaxf(m1, mx1);
        float a0 = __expf(m0 - mn0), a1 = __expf(m1 - mn1);

        float sum0 = 0.f, sum1 = 0.f;
        #pragma unroll
        for (int nt = 0; nt < 8; nt++) {
            sacc[nt][0] = __expf(sacc[nt][0] - mn0);
            sacc[nt][1] = __expf(sacc[nt][1] - mn0);
            sacc[nt][2] = __expf(sacc[nt][2] - mn1);
            sacc[nt][3] = __expf(sacc[nt][3] - mn1);
            sum0 += sacc[nt][0] + sacc[nt][1];
            sum1 += sacc[nt][2] + sacc[nt][3];
        }
        sum0 += __shfl_xor_sync(0xffffffffu, sum0, 1);
        sum0 += __shfl_xor_sync(0xffffffffu, sum0, 2);
        sum1 += __shfl_xor_sync(0xffffffffu, sum1, 1);
        sum1 += __shfl_xor_sync(0xffffffffu, sum1, 2);
        l0 = l0 * a0 + sum0;  m0 = mn0;
        l1 = l1 * a1 + sum1;  m1 = mn1;
        #pragma unroll
        for (int nt = 0; nt < 8; nt++) {
            oacc[nt][0] *= a0; oacc[nt][1] *= a0;
            oacc[nt][2] *= a1; oacc[nt][3] *= a1;
        }

        // ---- O += (Phi+Plo)(Vhi+Vlo), 3-pass; P frags from sacc ----
        int r_in = lane & 7, sel = lane >> 3;
        #pragma unroll
        for (int s = 0; s < 4; s++) {
            uint32_t pah[4], pal[4];
            #pragma unroll
            for (int half = 0; half < 2; half++) {
                float* pv = sacc[2*s + half];
                __nv_bfloat16 h0 = __float2bfloat16(pv[0]);
                __nv_bfloat16 h1 = __float2bfloat16(pv[1]);
                __nv_bfloat16 h2 = __float2bfloat16(pv[2]);
                __nv_bfloat16 h3 = __float2bfloat16(pv[3]);
                pah[half*2]   = pack2(h0, h1);
                pah[half*2+1] = pack2(h2, h3);
                pal[half*2]   = pack2(__float2bfloat16(pv[0] - __bfloat162float(h0)),
                                      __float2bfloat16(pv[1] - __bfloat162float(h1)));
                pal[half*2+1] = pack2(__float2bfloat16(pv[2] - __bfloat162float(h2)),
                                      __float2bfloat16(pv[3] - __bfloat162float(h3)));
            }
            int vrow = s * 16 + (sel & 1) * 8 + r_in;
            #pragma unroll
            for (int np = 0; np < 4; np++) {
                int cb = np * 32 + (sel >> 1) * 16;
                uint32_t off = SMEM_SWZ128((uint32_t)(vrow * 128 + cb));
                uint32_t vh[4], vl[4];
                ldsm_x4_t(vh, vbase + off);
                ldsm_x4_t(vl, vbase + 8192 + off);
                uint32_t vh0[2] = {vh[0], vh[1]}, vh1[2] = {vh[2], vh[3]};
                uint32_t vl0[2] = {vl[0], vl[1]}, vl1[2] = {vl[2], vl[3]};
                mma16816(oacc[2*np],   pah, vh0);
                mma16816(oacc[2*np],   pah, vl0);
                mma16816(oacc[2*np],   pal, vh0);
                mma16816(oacc[2*np+1], pah, vh1);
                mma16816(oacc[2*np+1], pah, vl1);
                mma16816(oacc[2*np+1], pal, vh1);
            }
        }
    }

    // ---- epilogue: O /= l, split bf16, write ----
    float inv0 = 1.0f / l0, inv1 = 1.0f / l1;
    int grow = b * SEQ + r0g;   // absolute output row
    #pragma unroll
    for (int nt = 0; nt < 8; nt++) {
        int col = h * DK + nt * 8 + 2 * (lane & 3);
        float v0 = oacc[nt][0] * inv0, v1 = oacc[nt][1] * inv0;
        float v2 = oacc[nt][2] * inv1, v3 = oacc[nt][3] * inv1;
        __nv_bfloat16 h0,lo0,h1,lo1,h2,lo2,h3,lo3;
        split_bf16(v0,h0,lo0); split_bf16(v1,h1,lo1);
        split_bf16(v2,h2,lo2); split_bf16(v3,h3,lo3);
        *reinterpret_cast<__nv_bfloat162*>(&Ohi[(size_t)grow * DMODEL + col])       = __nv_bfloat162(h0, h1);
        *reinterpret_cast<__nv_bfloat162*>(&Olo[(size_t)grow * DMODEL + col])       = __nv_bfloat162(lo0, lo1);
        *reinterpret_cast<__nv_bfloat162*>(&Ohi[(size_t)(grow + 8) * DMODEL + col]) = __nv_bfloat162(h2, h3);
        *reinterpret_cast<__nv_bfloat162*>(&Olo[(size_t)(grow + 8) * DMODEL + col]) = __nv_bfloat162(lo2, lo3);
    }
}

// ---------------- launch ----------------
extern "C" void kernel_launch(void* const* d_in, const int* in_sizes, int n_in,
                              void* d_out, int out_size)
{
    const float* x     = (const float*)d_in[0];
    const float* ln1_g = (const float*)d_in[1];
    const float* ln1_b = (const float*)d_in[2];
    const float* w_q   = (const float*)d_in[3];
    const float* w_k   = (const float*)d_in[4];
    const float* w_v   = (const float*)d_in[5];
    const float* w_o   = (const float*)d_in[6];
    const float* b_o   = (const float*)d_in[7];
    const float* ln2_g = (const float*)d_in[8];
    const float* ln2_b = (const float*)d_in[9];
    const float* w1    = (const float*)d_in[10];
    const float* b1    = (const float*)d_in[11];
    const float* w2    = (const float*)d_in[12];
    const float* b2    = (const float*)d_in[13];
    float* out = (float*)d_out;

    __nv_bfloat16 *hhi,*hlo,*qkvhi,*qkvlo,*atthi,*attlo,*ffnhi,*ffnlo;
    __nv_bfloat16 *wqkv_hi,*wqkv_lo,*wo_hi,*wo_lo,*w1_hi,*w1_lo,*w2_hi,*w2_lo;
    float *x1;
    cudaGetSymbolAddress((void**)&hhi,   g_hhi);   cudaGetSymbolAddress((void**)&hlo,   g_hlo);
    cudaGetSymbolAddress((void**)&qkvhi, g_qkvhi); cudaGetSymbolAddress((void**)&qkvlo, g_qkvlo);
    cudaGetSymbolAddress((void**)&atthi, g_atthi); cudaGetSymbolAddress((void**)&attlo, g_attlo);
    cudaGetSymbolAddress((void**)&x1,    g_x1);
    cudaGetSymbolAddress((void**)&ffnhi, g_ffnhi); cudaGetSymbolAddress((void**)&ffnlo, g_ffnlo);
    cudaGetSymbolAddress((void**)&wqkv_hi, g_wqkvT_hi); cudaGetSymbolAddress((void**)&wqkv_lo, g_wqkvT_lo);
    cudaGetSymbolAddress((void**)&wo_hi, g_woT_hi); cudaGetSymbolAddress((void**)&wo_lo, g_woT_lo);
    cudaGetSymbolAddress((void**)&w1_hi, g_w1T_hi); cudaGetSymbolAddress((void**)&w1_lo, g_w1T_lo);
    cudaGetSymbolAddress((void**)&w2_hi, g_w2T_hi); cudaGetSymbolAddress((void**)&w2_lo, g_w2T_lo);

    cudaFuncSetAttribute(attn_mma, cudaFuncAttributeMaxDynamicSharedMemorySize, ATT_SMEM);
    cudaFuncSetAttribute(mma_gemm<0>, cudaFuncAttributeMaxDynamicSharedMemorySize, MG_SMEM);
    cudaFuncSetAttribute(mma_gemm<1>, cudaFuncAttributeMaxDynamicSharedMemorySize, MG_SMEM);
    cudaFuncSetAttribute(mma_gemm<2>, cudaFuncAttributeMaxDynamicSharedMemorySize, MG_SMEM);

    dim3 tb(32, 8);
    dim3 gP(DMODEL / 128, ROWS / 128);    // (8, 64)
    dim3 gF1(FFN_DIM / 128, ROWS / 128);  // (32, 64)

    // Launches 1-3: QKV weight splits (into fused T buffer)
    wsplitT<<<dim3(DMODEL/32, DMODEL/32), tb>>>(w_q, wqkv_hi,                   wqkv_lo,                   DMODEL, DMODEL);
    wsplitT<<<dim3(DMODEL/32, DMODEL/32), tb>>>(w_k, wqkv_hi + DMODEL*DMODEL,   wqkv_lo + DMODEL*DMODEL,   DMODEL, DMODEL);
    wsplitT<<<dim3(DMODEL/32, DMODEL/32), tb>>>(w_v, wqkv_hi + 2*DMODEL*DMODEL, wqkv_lo + 2*DMODEL*DMODEL, DMODEL, DMODEL);
    // Launch 4: LN1
    ln_kernel<<<ROWS, 256>>>(x, ln1_g, ln1_b, hhi, hlo);
    // Launch 5: fused QKV projection -> split bf16
    mma_gemm<0><<<dim3(QKV_N/128, ROWS/128), 256, MG_SMEM>>>(hhi, hlo, wqkv_hi, wqkv_lo,
        nullptr, nullptr, nullptr, qkvhi, qkvlo, ROWS, QKV_N, DMODEL);
    // Launch 6 (ncu -s 5 -c 1 captures this): tensor-core attention
    attn_mma<<<dim3(SEQ / 64, BATCH * NHEAD), 128, ATT_SMEM>>>(qkvhi, qkvlo, atthi, attlo);
    // Launch 7: wo split
    wsplitT<<<dim3(DMODEL/32, DMODEL/32), tb>>>(w_o, wo_hi, wo_lo, DMODEL, DMODEL);
    // Launch 8: O projection + bias + residual -> x1 (fp32)
    mma_gemm<1><<<gP, 256, MG_SMEM>>>(atthi, attlo, wo_hi, wo_lo, b_o, x, x1, nullptr, nullptr, ROWS, DMODEL, DMODEL);
    // Launch 9: LN2
    ln_kernel<<<ROWS, 256>>>(x1, ln2_g, ln2_b, hhi, hlo);
    // Launch 10: w1 split
    wsplitT<<<dim3(FFN_DIM/32, DMODEL/32), tb>>>(w1, w1_hi, w1_lo, DMODEL, FFN_DIM);
    // Launch 11: FFN up + GELU -> split bf16
    mma_gemm<2><<<gF1, 256, MG_SMEM>>>(hhi, hlo, w1_hi, w1_lo, b1, nullptr, nullptr, ffnhi, ffnlo, ROWS, FFN_DIM, DMODEL);
    // Launch 12: w2 split
    wsplitT<<<dim3(DMODEL/32, FFN_DIM/32), tb>>>(w2, w2_hi, w2_lo, FFN_DIM, DMODEL);
    // Launch 13: FFN down + bias + residual -> out
    mma_gemm<1><<<gP, 256, MG_SMEM>>>(ffnhi, ffnlo, w2_hi, w2_lo, b2, x1, out, nullptr, nullptr, ROWS, DMODEL, FFN_DIM);
}

// round 5
// speedup vs baseline: 5.0764x; 1.4006x over previous
#include <cuda_runtime.h>
#include <cuda_fp16.h>
#include <math.h>
#include <stdint.h>

#define BATCH   16
#define SEQ     512
#define DMODEL  1024
#define NHEAD   16
#define DK      64
#define FFN_DIM 4096
#define ROWS    (BATCH * SEQ)        // 8192
#define QKV_N   (3 * DMODEL)         // 3072

// ---------------- scratch (device globals; no allocation) ----------------
__device__ __half g_hhi [ROWS * DMODEL];
__device__ __half g_hlo [ROWS * DMODEL];
__device__ __half g_qkvhi[ROWS * QKV_N];
__device__ __half g_qkvlo[ROWS * QKV_N];
__device__ __half g_atthi[ROWS * DMODEL];
__device__ __half g_attlo[ROWS * DMODEL];
__device__ float  g_x1 [ROWS * DMODEL];
__device__ __half g_ffnhi[ROWS * FFN_DIM];
__device__ __half g_ffnlo[ROWS * FFN_DIM];
// transposed fp16 weights: T[N,K] (single precision term)
__device__ __half g_wqkvT[QKV_N*DMODEL];
__device__ __half g_woT  [DMODEL*DMODEL];
__device__ __half g_w1T  [DMODEL*FFN_DIM];
__device__ __half g_w2T  [FFN_DIM*DMODEL];

// ---------------- helpers ----------------
__device__ __forceinline__ uint32_t smem_u32(const void* p) {
    uint32_t a;
    asm("{ .reg .u64 t; cvta.to.shared.u64 t, %1; cvt.u32.u64 %0, t; }" : "=r"(a) : "l"(p));
    return a;
}
#define CP_ASYNC16(dst, src) \
    asm volatile("cp.async.cg.shared.global [%0], [%1], 16;" :: "r"(dst), "l"(src) : "memory")
#define CP_COMMIT() asm volatile("cp.async.commit_group;" ::: "memory")
#define CP_WAIT(n)  asm volatile("cp.async.wait_group %0;" :: "n"(n) : "memory")
#define SMEM_SWZ128(off) ((off) ^ (((off) >> 3) & 0x70))

__device__ __forceinline__ void ldsm_x4(uint32_t* r, uint32_t addr) {
    asm volatile("ldmatrix.sync.aligned.m8n8.x4.shared.b16 {%0,%1,%2,%3}, [%4];"
        : "=r"(r[0]), "=r"(r[1]), "=r"(r[2]), "=r"(r[3]) : "r"(addr));
}
__device__ __forceinline__ void ldsm_x4_t(uint32_t* r, uint32_t addr) {
    asm volatile("ldmatrix.sync.aligned.m8n8.x4.trans.shared.b16 {%0,%1,%2,%3}, [%4];"
        : "=r"(r[0]), "=r"(r[1]), "=r"(r[2]), "=r"(r[3]) : "r"(addr));
}
__device__ __forceinline__ void mma16816(float* d, const uint32_t* a, const uint32_t* b) {
    asm volatile("mma.sync.aligned.m16n8k16.row.col.f32.f16.f16.f32 "
        "{%0,%1,%2,%3}, {%4,%5,%6,%7}, {%8,%9}, {%0,%1,%2,%3};"
        : "+f"(d[0]), "+f"(d[1]), "+f"(d[2]), "+f"(d[3])
        : "r"(a[0]), "r"(a[1]), "r"(a[2]), "r"(a[3]), "r"(b[0]), "r"(b[1]));
}

__device__ __forceinline__ float gelu_exact(float v) {
    return 0.5f * v * (1.0f + erff(v * 0.70710678118654752f));
}
__device__ __forceinline__ void split_f16(float v, __half& hi, __half& lo) {
    hi = __float2half(v);
    lo = __float2half(v - __half2float(hi));
}
__device__ __forceinline__ uint32_t pack2h(__half a, __half b) {
    __half2 t(a, b);
    return *reinterpret_cast<uint32_t*>(&t);
}

// ---------------- weight transpose + fp16 quantize: W[K,N] -> T[N,K] ----------------
__global__ void wsplitT(const float* __restrict__ W, __half* __restrict__ T, int K, int N)
{
    __shared__ float t[32][33];
    int n0 = blockIdx.x * 32, k0 = blockIdx.y * 32;
    int tx = threadIdx.x, ty = threadIdx.y;
    #pragma unroll
    for (int i = 0; i < 4; i++)
        t[ty + 8*i][tx] = W[(size_t)(k0 + ty + 8*i) * N + n0 + tx];
    __syncthreads();
    #pragma unroll
    for (int i = 0; i < 4; i++) {
        size_t o = (size_t)(n0 + ty + 8*i) * K + k0 + tx;
        T[o] = __float2half(t[tx][ty + 8*i]);
    }
}

// ---------------- LayerNorm: one block per row, outputs fp16 hi/lo ----------------
__global__ void ln_kernel(const float* __restrict__ x,
                          const float* __restrict__ g,
                          const float* __restrict__ b,
                          __half* __restrict__ ohi,
                          __half* __restrict__ olo)
{
    int row = blockIdx.x;
    const float4* xr = reinterpret_cast<const float4*>(x + (size_t)row * DMODEL);
    int t = threadIdx.x;
    float4 v = xr[t];
    float s  = v.x + v.y + v.z + v.w;
    float sq = v.x*v.x + v.y*v.y + v.z*v.z + v.w*v.w;

    __shared__ float red_s[8], red_q[8];
    for (int o = 16; o > 0; o >>= 1) {
        s  += __shfl_xor_sync(0xffffffffu, s,  o);
        sq += __shfl_xor_sync(0xffffffffu, sq, o);
    }
    int wid = t >> 5, lid = t & 31;
    if (lid == 0) { red_s[wid] = s; red_q[wid] = sq; }
    __syncthreads();
    if (wid == 0) {
        float ss = (lid < 8) ? red_s[lid] : 0.f;
        float qq = (lid < 8) ? red_q[lid] : 0.f;
        for (int o = 4; o > 0; o >>= 1) {
            ss += __shfl_xor_sync(0xffffffffu, ss, o);
            qq += __shfl_xor_sync(0xffffffffu, qq, o);
        }
        if (lid == 0) { red_s[0] = ss; red_q[0] = qq; }
    }
    __syncthreads();
    float mean = red_s[0] * (1.0f / DMODEL);
    float var  = red_q[0] * (1.0f / DMODEL) - mean * mean;
    float rstd = rsqrtf(var + 1e-5f);

    float4 gv = reinterpret_cast<const float4*>(g)[t];
    float4 bv = reinterpret_cast<const float4*>(b)[t];
    float o0 = (v.x - mean) * rstd * gv.x + bv.x;
    float o1 = (v.y - mean) * rstd * gv.y + bv.y;
    float o2 = (v.z - mean) * rstd * gv.z + bv.z;
    float o3 = (v.w - mean) * rstd * gv.w + bv.w;
    __half h0,l0,h1,l1,h2,l2,h3,l3;
    split_f16(o0,h0,l0); split_f16(o1,h1,l1); split_f16(o2,h2,l2); split_f16(o3,h3,l3);
    __half2* ph = reinterpret_cast<__half2*>(ohi + (size_t)row * DMODEL);
    __half2* pl = reinterpret_cast<__half2*>(olo + (size_t)row * DMODEL);
    ph[t*2]   = __half2(h0, h1);
    ph[t*2+1] = __half2(h2, h3);
    pl[t*2]   = __half2(l0, l1);
    pl[t*2+1] = __half2(l2, l3);
}

// ---------------- mma.sync fp16 2-pass GEMM (4-stage pipeline) ----------------
// C[M,N] = (Ahi+Alo)[M,K] @ B[N,K]^T   (B single fp16)
// CTA tile 128x128, KBLK=64, 8 warps (2 M x 4 N), warp tile 64x32.
// EPI: 0 = fp16 hi/lo split C; 1 = +bias +resid -> fp32 C; 2 = +bias, GELU -> fp16 hi/lo
#define KBLK 64
#define STAGE_BYTES 49152            // Ahi 16K | Alo 16K | B 16K
#define NSTAGE 4
#define MG_SMEM (NSTAGE * STAGE_BYTES)   // 196608

template<int EPI>
__global__ __launch_bounds__(256, 1)
void mma_gemm(const __half* __restrict__ Ahi, const __half* __restrict__ Alo,
              const __half* __restrict__ B,
              const float* __restrict__ bias, const float* __restrict__ resid,
              float* __restrict__ C, __half* __restrict__ Chi,
              __half* __restrict__ Clo, int M, int N, int K)
{
    extern __shared__ char sm[];
    uint32_t sb = smem_u32(sm);

    int tid  = threadIdx.x;
    int wid  = tid >> 5;
    int lane = tid & 31;
    int wm   = wid & 1;
    int wn   = wid >> 1;

    int row0 = blockIdx.y * 128, col0 = blockIdx.x * 128;
    const __half* pAhi = Ahi + (size_t)row0 * K;
    const __half* pAlo = Alo + (size_t)row0 * K;
    const __half* pB   = B   + (size_t)col0 * K;

    int KB = K / KBLK;

    int ld_r[4], ld_c[4];
    uint32_t ld_so[4];
    #pragma unroll
    for (int i = 0; i < 4; i++) {
        int idx = tid + (i << 8);
        ld_r[i] = idx >> 3;
        ld_c[i] = idx & 7;
        ld_so[i] = SMEM_SWZ128((uint32_t)(ld_r[i] * 128 + ld_c[i] * 16));
    }

    auto load_stage = [&](int kb) {
        uint32_t base = sb + (kb & (NSTAGE - 1)) * STAGE_BYTES;
        int koff = kb * KBLK;
        #pragma unroll
        for (int i = 0; i < 4; i++) {
            size_t go = (size_t)ld_r[i] * K + koff + ld_c[i] * 8;
            CP_ASYNC16(base + ld_so[i],         (const void*)(pAhi + go));
            CP_ASYNC16(base + 16384 + ld_so[i], (const void*)(pAlo + go));
            CP_ASYNC16(base + 32768 + ld_so[i], (const void*)(pB   + go));
        }
        CP_COMMIT();
    };

    float acc[4][4][4];
    #pragma unroll
    for (int i = 0; i < 4; i++)
        #pragma unroll
        for (int j = 0; j < 4; j++)
            #pragma unroll
            for (int e = 0; e < 4; e++) acc[i][j][e] = 0.f;

    load_stage(0);
    load_stage(1);
    load_stage(2);

    for (int kb = 0; kb < KB; kb++) {
        if (kb + 3 < KB) load_stage(kb + 3);
        else             CP_COMMIT();
        CP_WAIT(3);
        __syncthreads();

        uint32_t base = sb + (kb & (NSTAGE - 1)) * STAGE_BYTES;
        uint32_t sAh = base, sAl = base + 16384, sB = base + 32768;

        #pragma unroll
        for (int kk = 0; kk < 4; kk++) {
            uint32_t ah[4][4], al[4][4], bh[4][2];
            int acol2 = (kk * 16 + ((lane >> 4) << 3)) * 2;
            #pragma unroll
            for (int mt = 0; mt < 4; mt++) {
                int row = wm * 64 + mt * 16 + (lane & 15);
                uint32_t off = SMEM_SWZ128((uint32_t)(row * 128 + acol2));
                ldsm_x4(ah[mt], sAh + off);
                ldsm_x4(al[mt], sAl + off);
            }
            int bcol2 = (kk * 16 + (((lane >> 3) & 1) << 3)) * 2;
            int brow  = wn * 32 + ((lane >> 4) << 3) + (lane & 7);
            #pragma unroll
            for (int p = 0; p < 2; p++) {
                uint32_t off = SMEM_SWZ128((uint32_t)((brow + p * 16) * 128 + bcol2));
                uint32_t t[4];
                ldsm_x4(t, sB + off);
                bh[p*2][0] = t[0]; bh[p*2][1] = t[1]; bh[p*2+1][0] = t[2]; bh[p*2+1][1] = t[3];
            }
            #pragma unroll
            for (int mt = 0; mt < 4; mt++)
                #pragma unroll
                for (int nt = 0; nt < 4; nt++) {
                    mma16816(acc[mt][nt], ah[mt], bh[nt]);
                    mma16816(acc[mt][nt], al[mt], bh[nt]);
                }
        }
        __syncthreads();
    }

    // epilogue
    int g  = lane >> 2;
    int c2 = (lane & 3) * 2;
    #pragma unroll
    for (int mt = 0; mt < 4; mt++) {
        #pragma unroll
        for (int nt = 0; nt < 4; nt++) {
            int row = row0 + wm * 64 + mt * 16 + g;
            int col = col0 + wn * 32 + nt * 8 + c2;
            float d[4] = {acc[mt][nt][0], acc[mt][nt][1], acc[mt][nt][2], acc[mt][nt][3]};
            if (EPI >= 1) {
                float b0 = __ldg(&bias[col]), b1 = __ldg(&bias[col + 1]);
                d[0] += b0; d[1] += b1; d[2] += b0; d[3] += b1;
            }
            if (EPI == 1) {
                float2 r0 = *reinterpret_cast<const float2*>(&resid[(size_t)row * N + col]);
                float2 r1 = *reinterpret_cast<const float2*>(&resid[(size_t)(row + 8) * N + col]);
                d[0] += r0.x; d[1] += r0.y; d[2] += r1.x; d[3] += r1.y;
                *reinterpret_cast<float2*>(&C[(size_t)row * N + col])       = make_float2(d[0], d[1]);
                *reinterpret_cast<float2*>(&C[(size_t)(row + 8) * N + col]) = make_float2(d[2], d[3]);
            } else {
                if (EPI == 2) {
                    d[0] = gelu_exact(d[0]); d[1] = gelu_exact(d[1]);
                    d[2] = gelu_exact(d[2]); d[3] = gelu_exact(d[3]);
                }
                __half h0,l0,h1,l1,h2,l2,h3,l3;
                split_f16(d[0],h0,l0); split_f16(d[1],h1,l1);
                split_f16(d[2],h2,l2); split_f16(d[3],h3,l3);
                *reinterpret_cast<__half2*>(&Chi[(size_t)row * N + col])       = __half2(h0, h1);
                *reinterpret_cast<__half2*>(&Clo[(size_t)row * N + col])       = __half2(l0, l1);
                *reinterpret_cast<__half2*>(&Chi[(size_t)(row + 8) * N + col]) = __half2(h2, h3);
                *reinterpret_cast<__half2*>(&Clo[(size_t)(row + 8) * N + col]) = __half2(l2, l3);
            }
        }
    }
}

// ---------------- tensor-core causal flash attention (fp16, 3-pass) ----------------
// CTA: 128 threads (4 warps), one (b, h, qtile64). Warp w owns q rows [16w, 16w+16).
// smem: sQhi(8K) sQlo(8K) | stage s: Khi Klo Vhi Vlo (8K each), 2 stages.
#define ATT_SMEM (16384 + 2 * 32768)   // 81920

__global__ __launch_bounds__(128, 2)
void attn_mma(const __half* __restrict__ QKVhi,
              const __half* __restrict__ QKVlo,
              __half* __restrict__ Ohi,
              __half* __restrict__ Olo)
{
    extern __shared__ char sm[];
    uint32_t sb = smem_u32(sm);
    int tid = threadIdx.x, lane = tid & 31, w = tid >> 5;
    int bh = blockIdx.y, b = bh >> 4, h = bh & 15;
    int qt = blockIdx.x;
    const int QS = QKV_N;   // 3072

    // ---- issue Q loads ----
    {
        size_t q0 = (size_t)(b * SEQ + qt * 64) * QS + h * DK;
        #pragma unroll
        for (int i = 0; i < 4; i++) {
            int idx = tid + (i << 7);
            int r = idx >> 3, c = idx & 7;
            uint32_t so = SMEM_SWZ128((uint32_t)(r * 128 + c * 16));
            size_t go = q0 + (size_t)r * QS + c * 8;
            CP_ASYNC16(sb + so,        (const void*)(QKVhi + go));
            CP_ASYNC16(sb + 8192 + so, (const void*)(QKVlo + go));
        }
    }

    auto load_kv = [&](int kt) {
        uint32_t base = sb + 16384 + (kt & 1) * 32768;
        size_t k0 = (size_t)(b * SEQ + kt * 64) * QS + h * DK + DMODEL;
        size_t v0 = k0 + DMODEL;
        #pragma unroll
        for (int i = 0; i < 4; i++) {
            int idx = tid + (i << 7);
            int r = idx >> 3, c = idx & 7;
            uint32_t so = SMEM_SWZ128((uint32_t)(r * 128 + c * 16));
            size_t gk = k0 + (size_t)r * QS + c * 8;
            size_t gv = v0 + (size_t)r * QS + c * 8;
            CP_ASYNC16(base + so,         (const void*)(QKVhi + gk));
            CP_ASYNC16(base + 8192 + so,  (const void*)(QKVlo + gk));
            CP_ASYNC16(base + 16384 + so, (const void*)(QKVhi + gv));
            CP_ASYNC16(base + 24576 + so, (const void*)(QKVlo + gv));
        }
        CP_COMMIT();
    };

    load_kv(0);
    CP_WAIT(0);
    __syncthreads();

    // ---- hoist Q fragments ----
    uint32_t qh[4][4], ql[4][4];
    {
        int arow = w * 16 + (lane & 15);
        #pragma unroll
        for (int s = 0; s < 4; s++) {
            uint32_t off = SMEM_SWZ128((uint32_t)(arow * 128 + (s * 16 + ((lane >> 4) << 3)) * 2));
            ldsm_x4(qh[s], sb + off);
            ldsm_x4(ql[s], sb + 8192 + off);
        }
    }

    float oacc[8][4];
    #pragma unroll
    for (int i = 0; i < 8; i++)
        #pragma unroll
        for (int e = 0; e < 4; e++) oacc[i][e] = 0.f;
    float m0 = -1e30f, m1 = -1e30f, l0 = 0.f, l1 = 0.f;

    int r0g = qt * 64 + w * 16 + (lane >> 2);
    int r1g = r0g + 8;

    for (int kt = 0; kt <= qt; kt++) {
        if (kt > 0) { CP_WAIT(0); __syncthreads(); }
        if (kt < qt) load_kv(kt + 1);

        uint32_t kbase = sb + 16384 + (kt & 1) * 32768;
        uint32_t vbase = kbase + 16384;

        // ---- S = (Qhi+Qlo)(Khi+Klo)^T, 3-pass ----
        float sacc[8][4];
        #pragma unroll
        for (int i = 0; i < 8; i++)
            #pragma unroll
            for (int e = 0; e < 4; e++) sacc[i][e] = 0.f;

        int b_r = ((lane >> 4) << 3) + (lane & 7);
        #pragma unroll
        for (int s = 0; s < 4; s++) {
            int b_c2 = (s * 16 + (((lane >> 3) & 1) << 3)) * 2;
            #pragma unroll
            for (int np = 0; np < 4; np++) {
                uint32_t off = SMEM_SWZ128((uint32_t)((np * 16 + b_r) * 128 + b_c2));
                uint32_t th[4], tl[4];
                ldsm_x4(th, kbase + off);
                ldsm_x4(tl, kbase + 8192 + off);
                uint32_t kh0[2] = {th[0], th[1]}, kh1[2] = {th[2], th[3]};
                uint32_t kl0[2] = {tl[0], tl[1]}, kl1[2] = {tl[2], tl[3]};
                mma16816(sacc[2*np],   qh[s], kh0);
                mma16816(sacc[2*np],   qh[s], kl0);
                mma16816(sacc[2*np],   ql[s], kh0);
                mma16816(sacc[2*np+1], qh[s], kh1);
                mma16816(sacc[2*np+1], qh[s], kl1);
                mma16816(sacc[2*np+1], ql[s], kh1);
            }
        }

        // ---- scale + causal mask ----
        #pragma unroll
        for (int nt = 0; nt < 8; nt++)
            #pragma unroll
            for (int e = 0; e < 4; e++) sacc[nt][e] *= 0.125f;
        if (kt == qt) {
            #pragma unroll
            for (int nt = 0; nt < 8; nt++) {
                int colb = kt * 64 + nt * 8 + 2 * (lane & 3);
                #pragma unroll
                for (int e = 0; e < 2; e++) {
                    if (colb + e > r0g) sacc[nt][e]     = -1e30f;
                    if (colb + e > r1g) sacc[nt][2 + e] = -1e30f;
                }
            }
        }

        // ---- online softmax ----
        float mx0 = sacc[0][0], mx1 = sacc[0][2];
        #pragma unroll
        for (int nt = 0; nt < 8; nt++) {
            mx0 = fmaxf(mx0, fmaxf(sacc[nt][0], sacc[nt][1]));
            mx1 = fmaxf(mx1, fmaxf(sacc[nt][2], sacc[nt][3]));
        }
        mx0 = fmaxf(mx0, __shfl_xor_sync(0xffffffffu, mx0, 1));
        mx0 = fmaxf(mx0, __shfl_xor_sync(0xffffffffu, mx0, 2));
        mx1 = fmaxf(mx1, __shfl_xor_sync(0xffffffffu, mx1, 1));
        mx1 = fmaxf(mx1, __shfl_xor_sync(0xffffffffu, mx1, 2));
        float mn0 = fmaxf(m0, mx0), mn1 = fmaxf(m1, mx1);
        float a0 = __expf(m0 - mn0), a1 = __expf(m1 - mn1);

        float sum0 = 0.f, sum1 = 0.f;
        #pragma unroll
        for (int nt = 0; nt < 8; nt++) {
            sacc[nt][0] = __expf(sacc[nt][0] - mn0);
            sacc[nt][1] = __expf(sacc[nt][1] - mn0);
            sacc[nt][2] = __expf(sacc[nt][2] - mn1);
            sacc[nt][3] = __expf(sacc[nt][3] - mn1);
            sum0 += sacc[nt][0] + sacc[nt][1];
            sum1 += sacc[nt][2] + sacc[nt][3];
        }
        sum0 += __shfl_xor_sync(0xffffffffu, sum0, 1);
        sum0 += __shfl_xor_sync(0xffffffffu, sum0, 2);
        sum1 += __shfl_xor_sync(0xffffffffu, sum1, 1);
        sum1 += __shfl_xor_sync(0xffffffffu, sum1, 2);
        l0 = l0 * a0 + sum0;  m0 = mn0;
        l1 = l1 * a1 + sum1;  m1 = mn1;
        #pragma unroll
        for (int nt = 0; nt < 8; nt++) {
            oacc[nt][0] *= a0; oacc[nt][1] *= a0;
            oacc[nt][2] *= a1; oacc[nt][3] *= a1;
        }

        // ---- O += (Phi+Plo)(Vhi+Vlo), 3-pass; P frags from sacc ----
        int r_in = lane & 7, sel = lane >> 3;
        #pragma unroll
        for (int s = 0; s < 4; s++) {
            uint32_t pah[4], pal[4];
            #pragma unroll
            for (int half = 0; half < 2; half++) {
                float* pv = sacc[2*s + half];
                __half h0 = __float2half(pv[0]);
                __half h1 = __float2half(pv[1]);
                __half h2 = __float2half(pv[2]);
                __half h3 = __float2half(pv[3]);
                pah[half*2]   = pack2h(h0, h1);
                pah[half*2+1] = pack2h(h2, h3);
                pal[half*2]   = pack2h(__float2half(pv[0] - __half2float(h0)),
                                       __float2half(pv[1] - __half2float(h1)));
                pal[half*2+1] = pack2h(__float2half(pv[2] - __half2float(h2)),
                                       __float2half(pv[3] - __half2float(h3)));
            }
            int vrow = s * 16 + (sel & 1) * 8 + r_in;
            #pragma unroll
            for (int np = 0; np < 4; np++) {
                int cb = np * 32 + (sel >> 1) * 16;
                uint32_t off = SMEM_SWZ128((uint32_t)(vrow * 128 + cb));
                uint32_t vh[4], vl[4];
                ldsm_x4_t(vh, vbase + off);
                ldsm_x4_t(vl, vbase + 8192 + off);
                uint32_t vh0[2] = {vh[0], vh[1]}, vh1[2] = {vh[2], vh[3]};
                uint32_t vl0[2] = {vl[0], vl[1]}, vl1[2] = {vl[2], vl[3]};
                mma16816(oacc[2*np],   pah, vh0);
                mma16816(oacc[2*np],   pah, vl0);
                mma16816(oacc[2*np],   pal, vh0);
                mma16816(oacc[2*np+1], pah, vh1);
                mma16816(oacc[2*np+1], pah, vl1);
                mma16816(oacc[2*np+1], pal, vh1);
            }
        }
    }

    // ---- epilogue: O /= l, split fp16, write ----
    float inv0 = 1.0f / l0, inv1 = 1.0f / l1;
    int grow = b * SEQ + r0g;
    #pragma unroll
    for (int nt = 0; nt < 8; nt++) {
        int col = h * DK + nt * 8 + 2 * (lane & 3);
        float v0 = oacc[nt][0] * inv0, v1 = oacc[nt][1] * inv0;
        float v2 = oacc[nt][2] * inv1, v3 = oacc[nt][3] * inv1;
        __half h0,lo0,h1,lo1,h2,lo2,h3,lo3;
        split_f16(v0,h0,lo0); split_f16(v1,h1,lo1);
        split_f16(v2,h2,lo2); split_f16(v3,h3,lo3);
        *reinterpret_cast<__half2*>(&Ohi[(size_t)grow * DMODEL + col])       = __half2(h0, h1);
        *reinterpret_cast<__half2*>(&Olo[(size_t)grow * DMODEL + col])       = __half2(lo0, lo1);
        *reinterpret_cast<__half2*>(&Ohi[(size_t)(grow + 8) * DMODEL + col]) = __half2(h2, h3);
        *reinterpret_cast<__half2*>(&Olo[(size_t)(grow + 8) * DMODEL + col]) = __half2(lo2, lo3);
    }
}

// ---------------- launch ----------------
extern "C" void kernel_launch(void* const* d_in, const int* in_sizes, int n_in,
                              void* d_out, int out_size)
{
    const float* x     = (const float*)d_in[0];
    const float* ln1_g = (const float*)d_in[1];
    const float* ln1_b = (const float*)d_in[2];
    const float* w_q   = (const float*)d_in[3];
    const float* w_k   = (const float*)d_in[4];
    const float* w_v   = (const float*)d_in[5];
    const float* w_o   = (const float*)d_in[6];
    const float* b_o   = (const float*)d_in[7];
    const float* ln2_g = (const float*)d_in[8];
    const float* ln2_b = (const float*)d_in[9];
    const float* w1    = (const float*)d_in[10];
    const float* b1    = (const float*)d_in[11];
    const float* w2    = (const float*)d_in[12];
    const float* b2    = (const float*)d_in[13];
    float* out = (float*)d_out;

    __half *hhi,*hlo,*qkvhi,*qkvlo,*atthi,*attlo,*ffnhi,*ffnlo;
    __half *wqkv,*wo,*w1t,*w2t;
    float *x1;
    cudaGetSymbolAddress((void**)&hhi,   g_hhi);   cudaGetSymbolAddress((void**)&hlo,   g_hlo);
    cudaGetSymbolAddress((void**)&qkvhi, g_qkvhi); cudaGetSymbolAddress((void**)&qkvlo, g_qkvlo);
    cudaGetSymbolAddress((void**)&atthi, g_atthi); cudaGetSymbolAddress((void**)&attlo, g_attlo);
    cudaGetSymbolAddress((void**)&x1,    g_x1);
    cudaGetSymbolAddress((void**)&ffnhi, g_ffnhi); cudaGetSymbolAddress((void**)&ffnlo, g_ffnlo);
    cudaGetSymbolAddress((void**)&wqkv,  g_wqkvT);
    cudaGetSymbolAddress((void**)&wo,    g_woT);
    cudaGetSymbolAddress((void**)&w1t,   g_w1T);
    cudaGetSymbolAddress((void**)&w2t,   g_w2T);

    cudaFuncSetAttribute(attn_mma, cudaFuncAttributeMaxDynamicSharedMemorySize, ATT_SMEM);
    cudaFuncSetAttribute(mma_gemm<0>, cudaFuncAttributeMaxDynamicSharedMemorySize, MG_SMEM);
    cudaFuncSetAttribute(mma_gemm<1>, cudaFuncAttributeMaxDynamicSharedMemorySize, MG_SMEM);
    cudaFuncSetAttribute(mma_gemm<2>, cudaFuncAttributeMaxDynamicSharedMemorySize, MG_SMEM);

    dim3 tb(32, 8);
    dim3 gP(DMODEL / 128, ROWS / 128);    // (8, 64)
    dim3 gF1(FFN_DIM / 128, ROWS / 128);  // (32, 64)

    // weight transpose + fp16 quantize
    wsplitT<<<dim3(DMODEL/32, DMODEL/32), tb>>>(w_q, wqkv,                   DMODEL, DMODEL);
    wsplitT<<<dim3(DMODEL/32, DMODEL/32), tb>>>(w_k, wqkv + DMODEL*DMODEL,   DMODEL, DMODEL);
    wsplitT<<<dim3(DMODEL/32, DMODEL/32), tb>>>(w_v, wqkv + 2*DMODEL*DMODEL, DMODEL, DMODEL);
    wsplitT<<<dim3(DMODEL/32, DMODEL/32), tb>>>(w_o, wo,  DMODEL, DMODEL);
    wsplitT<<<dim3(FFN_DIM/32, DMODEL/32), tb>>>(w1, w1t, DMODEL, FFN_DIM);
    wsplitT<<<dim3(DMODEL/32, FFN_DIM/32), tb>>>(w2, w2t, FFN_DIM, DMODEL);
    // LN1
    ln_kernel<<<ROWS, 256>>>(x, ln1_g, ln1_b, hhi, hlo);
    // fused QKV projection -> fp16 hi/lo
    mma_gemm<0><<<dim3(QKV_N/128, ROWS/128), 256, MG_SMEM>>>(hhi, hlo, wqkv,
        nullptr, nullptr, nullptr, qkvhi, qkvlo, ROWS, QKV_N, DMODEL);
    // tensor-core attention -> fp16 hi/lo
    attn_mma<<<dim3(SEQ / 64, BATCH * NHEAD), 128, ATT_SMEM>>>(qkvhi, qkvlo, atthi, attlo);
    // O projection + bias + residual -> x1 (fp32)
    mma_gemm<1><<<gP, 256, MG_SMEM>>>(atthi, attlo, wo, b_o, x, x1, nullptr, nullptr, ROWS, DMODEL, DMODEL);
    // LN2
    ln_kernel<<<ROWS, 256>>>(x1, ln2_g, ln2_b, hhi, hlo);
    // FFN up + GELU -> fp16 hi/lo
    mma_gemm<2><<<gF1, 256, MG_SMEM>>>(hhi, hlo, w1t, b1, nullptr, nullptr, ffnhi, ffnlo, ROWS, FFN_DIM, DMODEL);
    // FFN down + bias + residual -> out
    mma_gemm<1><<<gP, 256, MG_SMEM>>>(ffnhi, ffnlo, w2t, b2, x1, out, nullptr, nullptr, ROWS, DMODEL, FFN_DIM);
}

// round 6
// speedup vs baseline: 8.2978x; 1.6346x over previous
#include <cuda_runtime.h>
#include <cuda_fp16.h>
#include <math.h>
#include <stdint.h>

#define BATCH   16
#define SEQ     512
#define DMODEL  1024
#define NHEAD   16
#define DK      64
#define FFN_DIM 4096
#define ROWS    (BATCH * SEQ)        // 8192
#define QKV_N   (3 * DMODEL)         // 3072

// ---------------- scratch (device globals; no allocation) ----------------
__device__ __half g_h   [ROWS * DMODEL];
__device__ __half g_qkv [ROWS * QKV_N];
__device__ __half g_att [ROWS * DMODEL];
__device__ float  g_x1  [ROWS * DMODEL];
__device__ __half g_ffn [ROWS * FFN_DIM];
// transposed fp16 weights: T[N,K]
__device__ __half g_wqkvT[QKV_N*DMODEL];
__device__ __half g_woT  [DMODEL*DMODEL];
__device__ __half g_w1T  [DMODEL*FFN_DIM];
__device__ __half g_w2T  [FFN_DIM*DMODEL];

// ---------------- helpers ----------------
__device__ __forceinline__ uint32_t smem_u32(const void* p) {
    uint32_t a;
    asm("{ .reg .u64 t; cvta.to.shared.u64 t, %1; cvt.u32.u64 %0, t; }" : "=r"(a) : "l"(p));
    return a;
}
#define CP_ASYNC16(dst, src) \
    asm volatile("cp.async.cg.shared.global [%0], [%1], 16;" :: "r"(dst), "l"(src) : "memory")
#define CP_COMMIT() asm volatile("cp.async.commit_group;" ::: "memory")
#define CP_WAIT(n)  asm volatile("cp.async.wait_group %0;" :: "n"(n) : "memory")
#define SMEM_SWZ128(off) ((off) ^ (((off) >> 3) & 0x70))

__device__ __forceinline__ void ldsm_x4(uint32_t* r, uint32_t addr) {
    asm volatile("ldmatrix.sync.aligned.m8n8.x4.shared.b16 {%0,%1,%2,%3}, [%4];"
        : "=r"(r[0]), "=r"(r[1]), "=r"(r[2]), "=r"(r[3]) : "r"(addr));
}
__device__ __forceinline__ void ldsm_x4_t(uint32_t* r, uint32_t addr) {
    asm volatile("ldmatrix.sync.aligned.m8n8.x4.trans.shared.b16 {%0,%1,%2,%3}, [%4];"
        : "=r"(r[0]), "=r"(r[1]), "=r"(r[2]), "=r"(r[3]) : "r"(addr));
}
__device__ __forceinline__ void mma16816(float* d, const uint32_t* a, const uint32_t* b) {
    asm volatile("mma.sync.aligned.m16n8k16.row.col.f32.f16.f16.f32 "
        "{%0,%1,%2,%3}, {%4,%5,%6,%7}, {%8,%9}, {%0,%1,%2,%3};"
        : "+f"(d[0]), "+f"(d[1]), "+f"(d[2]), "+f"(d[3])
        : "r"(a[0]), "r"(a[1]), "r"(a[2]), "r"(a[3]), "r"(b[0]), "r"(b[1]));
}

__device__ __forceinline__ float gelu_exact(float v) {
    return 0.5f * v * (1.0f + erff(v * 0.70710678118654752f));
}
__device__ __forceinline__ uint32_t pack2h(__half a, __half b) {
    __half2 t(a, b);
    return *reinterpret_cast<uint32_t*>(&t);
}

// ---------------- weight transpose + fp16 quantize: W[K,N] -> T[N,K] ----------------
__global__ void wsplitT(const float* __restrict__ W, __half* __restrict__ T, int K, int N)
{
    __shared__ float t[32][33];
    int n0 = blockIdx.x * 32, k0 = blockIdx.y * 32;
    int tx = threadIdx.x, ty = threadIdx.y;
    #pragma unroll
    for (int i = 0; i < 4; i++)
        t[ty + 8*i][tx] = W[(size_t)(k0 + ty + 8*i) * N + n0 + tx];
    __syncthreads();
    #pragma unroll
    for (int i = 0; i < 4; i++) {
        size_t o = (size_t)(n0 + ty + 8*i) * K + k0 + tx;
        T[o] = __float2half(t[tx][ty + 8*i]);
    }
}

// ---------------- LayerNorm: one block per row, outputs fp16 ----------------
__global__ void ln_kernel(const float* __restrict__ x,
                          const float* __restrict__ g,
                          const float* __restrict__ b,
                          __half* __restrict__ oh)
{
    int row = blockIdx.x;
    const float4* xr = reinterpret_cast<const float4*>(x + (size_t)row * DMODEL);
    int t = threadIdx.x;
    float4 v = xr[t];
    float s  = v.x + v.y + v.z + v.w;
    float sq = v.x*v.x + v.y*v.y + v.z*v.z + v.w*v.w;

    __shared__ float red_s[8], red_q[8];
    for (int o = 16; o > 0; o >>= 1) {
        s  += __shfl_xor_sync(0xffffffffu, s,  o);
        sq += __shfl_xor_sync(0xffffffffu, sq, o);
    }
    int wid = t >> 5, lid = t & 31;
    if (lid == 0) { red_s[wid] = s; red_q[wid] = sq; }
    __syncthreads();
    if (wid == 0) {
        float ss = (lid < 8) ? red_s[lid] : 0.f;
        float qq = (lid < 8) ? red_q[lid] : 0.f;
        for (int o = 4; o > 0; o >>= 1) {
            ss += __shfl_xor_sync(0xffffffffu, ss, o);
            qq += __shfl_xor_sync(0xffffffffu, qq, o);
        }
        if (lid == 0) { red_s[0] = ss; red_q[0] = qq; }
    }
    __syncthreads();
    float mean = red_s[0] * (1.0f / DMODEL);
    float var  = red_q[0] * (1.0f / DMODEL) - mean * mean;
    float rstd = rsqrtf(var + 1e-5f);

    float4 gv = reinterpret_cast<const float4*>(g)[t];
    float4 bv = reinterpret_cast<const float4*>(b)[t];
    float o0 = (v.x - mean) * rstd * gv.x + bv.x;
    float o1 = (v.y - mean) * rstd * gv.y + bv.y;
    float o2 = (v.z - mean) * rstd * gv.z + bv.z;
    float o3 = (v.w - mean) * rstd * gv.w + bv.w;
    __half2* ph = reinterpret_cast<__half2*>(oh + (size_t)row * DMODEL);
    ph[t*2]   = __half2(__float2half(o0), __float2half(o1));
    ph[t*2+1] = __half2(__float2half(o2), __float2half(o3));
}

// ---------------- mma.sync fp16 1-pass GEMM (4-stage pipeline) ----------------
// C[M,N] = A[M,K] @ B[N,K]^T
// CTA tile 128x128, KBLK=64, 8 warps (2 M x 4 N), warp tile 64x32.
// EPI: 0 = fp16 C; 1 = +bias +resid -> fp32 C; 2 = +bias, GELU -> fp16 C
#define KBLK 64
#define STAGE_BYTES 32768            // A 16K | B 16K
#define NSTAGE 4
#define MG_SMEM (NSTAGE * STAGE_BYTES)   // 131072

template<int EPI>
__global__ __launch_bounds__(256, 1)
void mma_gemm(const __half* __restrict__ A, const __half* __restrict__ B,
              const float* __restrict__ bias, const float* __restrict__ resid,
              float* __restrict__ C, __half* __restrict__ Ch,
              int M, int N, int K)
{
    extern __shared__ char sm[];
    uint32_t sb = smem_u32(sm);

    int tid  = threadIdx.x;
    int wid  = tid >> 5;
    int lane = tid & 31;
    int wm   = wid & 1;
    int wn   = wid >> 1;

    int row0 = blockIdx.y * 128, col0 = blockIdx.x * 128;
    const __half* pA = A + (size_t)row0 * K;
    const __half* pB = B + (size_t)col0 * K;

    int KB = K / KBLK;

    int ld_r[4], ld_c[4];
    uint32_t ld_so[4];
    #pragma unroll
    for (int i = 0; i < 4; i++) {
        int idx = tid + (i << 8);
        ld_r[i] = idx >> 3;
        ld_c[i] = idx & 7;
        ld_so[i] = SMEM_SWZ128((uint32_t)(ld_r[i] * 128 + ld_c[i] * 16));
    }

    auto load_stage = [&](int kb) {
        uint32_t base = sb + (kb & (NSTAGE - 1)) * STAGE_BYTES;
        int koff = kb * KBLK;
        #pragma unroll
        for (int i = 0; i < 4; i++) {
            size_t go = (size_t)ld_r[i] * K + koff + ld_c[i] * 8;
            CP_ASYNC16(base + ld_so[i],         (const void*)(pA + go));
            CP_ASYNC16(base + 16384 + ld_so[i], (const void*)(pB + go));
        }
        CP_COMMIT();
    };

    float acc[4][4][4];
    #pragma unroll
    for (int i = 0; i < 4; i++)
        #pragma unroll
        for (int j = 0; j < 4; j++)
            #pragma unroll
            for (int e = 0; e < 4; e++) acc[i][j][e] = 0.f;

    load_stage(0);
    load_stage(1);
    load_stage(2);

    for (int kb = 0; kb < KB; kb++) {
        if (kb + 3 < KB) load_stage(kb + 3);
        else             CP_COMMIT();
        CP_WAIT(3);
        __syncthreads();

        uint32_t base = sb + (kb & (NSTAGE - 1)) * STAGE_BYTES;
        uint32_t sA = base, sB = base + 16384;

        #pragma unroll
        for (int kk = 0; kk < 4; kk++) {
            uint32_t ah[4][4], bh[4][2];
            int acol2 = (kk * 16 + ((lane >> 4) << 3)) * 2;
            #pragma unroll
            for (int mt = 0; mt < 4; mt++) {
                int row = wm * 64 + mt * 16 + (lane & 15);
                uint32_t off = SMEM_SWZ128((uint32_t)(row * 128 + acol2));
                ldsm_x4(ah[mt], sA + off);
            }
            int bcol2 = (kk * 16 + (((lane >> 3) & 1) << 3)) * 2;
            int brow  = wn * 32 + ((lane >> 4) << 3) + (lane & 7);
            #pragma unroll
            for (int p = 0; p < 2; p++) {
                uint32_t off = SMEM_SWZ128((uint32_t)((brow + p * 16) * 128 + bcol2));
                uint32_t t[4];
                ldsm_x4(t, sB + off);
                bh[p*2][0] = t[0]; bh[p*2][1] = t[1]; bh[p*2+1][0] = t[2]; bh[p*2+1][1] = t[3];
            }
            #pragma unroll
            for (int mt = 0; mt < 4; mt++)
                #pragma unroll
                for (int nt = 0; nt < 4; nt++)
                    mma16816(acc[mt][nt], ah[mt], bh[nt]);
        }
        __syncthreads();
    }

    // epilogue
    int g  = lane >> 2;
    int c2 = (lane & 3) * 2;
    #pragma unroll
    for (int mt = 0; mt < 4; mt++) {
        #pragma unroll
        for (int nt = 0; nt < 4; nt++) {
            int row = row0 + wm * 64 + mt * 16 + g;
            int col = col0 + wn * 32 + nt * 8 + c2;
            float d[4] = {acc[mt][nt][0], acc[mt][nt][1], acc[mt][nt][2], acc[mt][nt][3]};
            if (EPI >= 1) {
                float b0 = __ldg(&bias[col]), b1 = __ldg(&bias[col + 1]);
                d[0] += b0; d[1] += b1; d[2] += b0; d[3] += b1;
            }
            if (EPI == 1) {
                float2 r0 = *reinterpret_cast<const float2*>(&resid[(size_t)row * N + col]);
                float2 r1 = *reinterpret_cast<const float2*>(&resid[(size_t)(row + 8) * N + col]);
                d[0] += r0.x; d[1] += r0.y; d[2] += r1.x; d[3] += r1.y;
                *reinterpret_cast<float2*>(&C[(size_t)row * N + col])       = make_float2(d[0], d[1]);
                *reinterpret_cast<float2*>(&C[(size_t)(row + 8) * N + col]) = make_float2(d[2], d[3]);
            } else {
                if (EPI == 2) {
                    d[0] = gelu_exact(d[0]); d[1] = gelu_exact(d[1]);
                    d[2] = gelu_exact(d[2]); d[3] = gelu_exact(d[3]);
                }
                *reinterpret_cast<__half2*>(&Ch[(size_t)row * N + col]) =
                    __half2(__float2half(d[0]), __float2half(d[1]));
                *reinterpret_cast<__half2*>(&Ch[(size_t)(row + 8) * N + col]) =
                    __half2(__float2half(d[2]), __float2half(d[3]));
            }
        }
    }
}

// ---------------- tensor-core causal flash attention (fp16, 1-pass) ----------------
// CTA: 128 threads (4 warps), one (b, h, qtile64). Warp w owns q rows [16w, 16w+16).
// smem: sQ(8K) | stage s: K(8K) V(8K), 2 stages.
#define ATT_SMEM (8192 + 2 * 16384)   // 40960

__global__ __launch_bounds__(128, 4)
void attn_mma(const __half* __restrict__ QKV,
              __half* __restrict__ O)
{
    extern __shared__ char sm[];
    uint32_t sb = smem_u32(sm);
    int tid = threadIdx.x, lane = tid & 31, w = tid >> 5;
    int bh = blockIdx.y, b = bh >> 4, h = bh & 15;
    int qt = blockIdx.x;
    const int QS = QKV_N;   // 3072

    // ---- issue Q loads ----
    {
        size_t q0 = (size_t)(b * SEQ + qt * 64) * QS + h * DK;
        #pragma unroll
        for (int i = 0; i < 4; i++) {
            int idx = tid + (i << 7);
            int r = idx >> 3, c = idx & 7;
            uint32_t so = SMEM_SWZ128((uint32_t)(r * 128 + c * 16));
            CP_ASYNC16(sb + so, (const void*)(QKV + q0 + (size_t)r * QS + c * 8));
        }
    }

    auto load_kv = [&](int kt) {
        uint32_t base = sb + 8192 + (kt & 1) * 16384;
        size_t k0 = (size_t)(b * SEQ + kt * 64) * QS + h * DK + DMODEL;
        size_t v0 = k0 + DMODEL;
        #pragma unroll
        for (int i = 0; i < 4; i++) {
            int idx = tid + (i << 7);
            int r = idx >> 3, c = idx & 7;
            uint32_t so = SMEM_SWZ128((uint32_t)(r * 128 + c * 16));
            CP_ASYNC16(base + so,        (const void*)(QKV + k0 + (size_t)r * QS + c * 8));
            CP_ASYNC16(base + 8192 + so, (const void*)(QKV + v0 + (size_t)r * QS + c * 8));
        }
        CP_COMMIT();
    };

    load_kv(0);
    CP_WAIT(0);
    __syncthreads();

    // ---- hoist Q fragments ----
    uint32_t qh[4][4];
    {
        int arow = w * 16 + (lane & 15);
        #pragma unroll
        for (int s = 0; s < 4; s++) {
            uint32_t off = SMEM_SWZ128((uint32_t)(arow * 128 + (s * 16 + ((lane >> 4) << 3)) * 2));
            ldsm_x4(qh[s], sb + off);
        }
    }

    float oacc[8][4];
    #pragma unroll
    for (int i = 0; i < 8; i++)
        #pragma unroll
        for (int e = 0; e < 4; e++) oacc[i][e] = 0.f;
    float m0 = -1e30f, m1 = -1e30f, l0 = 0.f, l1 = 0.f;

    int r0g = qt * 64 + w * 16 + (lane >> 2);
    int r1g = r0g + 8;

    for (int kt = 0; kt <= qt; kt++) {
        if (kt > 0) { CP_WAIT(0); __syncthreads(); }
        if (kt < qt) load_kv(kt + 1);

        uint32_t kbase = sb + 8192 + (kt & 1) * 16384;
        uint32_t vbase = kbase + 8192;

        // ---- S = Q K^T ----
        float sacc[8][4];
        #pragma unroll
        for (int i = 0; i < 8; i++)
            #pragma unroll
            for (int e = 0; e < 4; e++) sacc[i][e] = 0.f;

        int b_r = ((lane >> 4) << 3) + (lane & 7);
        #pragma unroll
        for (int s = 0; s < 4; s++) {
            int b_c2 = (s * 16 + (((lane >> 3) & 1) << 3)) * 2;
            #pragma unroll
            for (int np = 0; np < 4; np++) {
                uint32_t off = SMEM_SWZ128((uint32_t)((np * 16 + b_r) * 128 + b_c2));
                uint32_t th[4];
                ldsm_x4(th, kbase + off);
                uint32_t kh0[2] = {th[0], th[1]}, kh1[2] = {th[2], th[3]};
                mma16816(sacc[2*np],   qh[s], kh0);
                mma16816(sacc[2*np+1], qh[s], kh1);
            }
        }

        // ---- scale + causal mask ----
        #pragma unroll
        for (int nt = 0; nt < 8; nt++)
            #pragma unroll
            for (int e = 0; e < 4; e++) sacc[nt][e] *= 0.125f;
        if (kt == qt) {
            #pragma unroll
            for (int nt = 0; nt < 8; nt++) {
                int colb = kt * 64 + nt * 8 + 2 * (lane & 3);
                #pragma unroll
                for (int e = 0; e < 2; e++) {
                    if (colb + e > r0g) sacc[nt][e]     = -1e30f;
                    if (colb + e > r1g) sacc[nt][2 + e] = -1e30f;
                }
            }
        }

        // ---- online softmax ----
        float mx0 = sacc[0][0], mx1 = sacc[0][2];
        #pragma unroll
        for (int nt = 0; nt < 8; nt++) {
            mx0 = fmaxf(mx0, fmaxf(sacc[nt][0], sacc[nt][1]));
            mx1 = fmaxf(mx1, fmaxf(sacc[nt][2], sacc[nt][3]));
        }
        mx0 = fmaxf(mx0, __shfl_xor_sync(0xffffffffu, mx0, 1));
        mx0 = fmaxf(mx0, __shfl_xor_sync(0xffffffffu, mx0, 2));
        mx1 = fmaxf(mx1, __shfl_xor_sync(0xffffffffu, mx1, 1));
        mx1 = fmaxf(mx1, __shfl_xor_sync(0xffffffffu, mx1, 2));
        float mn0 = fmaxf(m0, mx0), mn1 = fmaxf(m1, mx1);
        float a0 = __expf(m0 - mn0), a1 = __expf(m1 - mn1);

        float sum0 = 0.f, sum1 = 0.f;
        #pragma unroll
        for (int nt = 0; nt < 8; nt++) {
            sacc[nt][0] = __expf(sacc[nt][0] - mn0);
            sacc[nt][1] = __expf(sacc[nt][1] - mn0);
            sacc[nt][2] = __expf(sacc[nt][2] - mn1);
            sacc[nt][3] = __expf(sacc[nt][3] - mn1);
            sum0 += sacc[nt][0] + sacc[nt][1];
            sum1 += sacc[nt][2] + sacc[nt][3];
        }
        sum0 += __shfl_xor_sync(0xffffffffu, sum0, 1);
        sum0 += __shfl_xor_sync(0xffffffffu, sum0, 2);
        sum1 += __shfl_xor_sync(0xffffffffu, sum1, 1);
        sum1 += __shfl_xor_sync(0xffffffffu, sum1, 2);
        l0 = l0 * a0 + sum0;  m0 = mn0;
        l1 = l1 * a1 + sum1;  m1 = mn1;
        #pragma unroll
        for (int nt = 0; nt < 8; nt++) {
            oacc[nt][0] *= a0; oacc[nt][1] *= a0;
            oacc[nt][2] *= a1; oacc[nt][3] *= a1;
        }

        // ---- O += P V ----
        int r_in = lane & 7, sel = lane >> 3;
        #pragma unroll
        for (int s = 0; s < 4; s++) {
            uint32_t pah[4];
            #pragma unroll
            for (int half = 0; half < 2; half++) {
                float* pv = sacc[2*s + half];
                pah[half*2]   = pack2h(__float2half(pv[0]), __float2half(pv[1]));
                pah[half*2+1] = pack2h(__float2half(pv[2]), __float2half(pv[3]));
            }
            int vrow = s * 16 + (sel & 1) * 8 + r_in;
            #pragma unroll
            for (int np = 0; np < 4; np++) {
                int cb = np * 32 + (sel >> 1) * 16;
                uint32_t off = SMEM_SWZ128((uint32_t)(vrow * 128 + cb));
                uint32_t vh[4];
                ldsm_x4_t(vh, vbase + off);
                uint32_t vh0[2] = {vh[0], vh[1]}, vh1[2] = {vh[2], vh[3]};
                mma16816(oacc[2*np],   pah, vh0);
                mma16816(oacc[2*np+1], pah, vh1);
            }
        }
    }

    // ---- epilogue: O /= l, write fp16 ----
    float inv0 = 1.0f / l0, inv1 = 1.0f / l1;
    int grow = b * SEQ + r0g;
    #pragma unroll
    for (int nt = 0; nt < 8; nt++) {
        int col = h * DK + nt * 8 + 2 * (lane & 3);
        *reinterpret_cast<__half2*>(&O[(size_t)grow * DMODEL + col]) =
            __half2(__float2half(oacc[nt][0] * inv0), __float2half(oacc[nt][1] * inv0));
        *reinterpret_cast<__half2*>(&O[(size_t)(grow + 8) * DMODEL + col]) =
            __half2(__float2half(oacc[nt][2] * inv1), __float2half(oacc[nt][3] * inv1));
    }
}

// ---------------- launch ----------------
extern "C" void kernel_launch(void* const* d_in, const int* in_sizes, int n_in,
                              void* d_out, int out_size)
{
    const float* x     = (const float*)d_in[0];
    const float* ln1_g = (const float*)d_in[1];
    const float* ln1_b = (const float*)d_in[2];
    const float* w_q   = (const float*)d_in[3];
    const float* w_k   = (const float*)d_in[4];
    const float* w_v   = (const float*)d_in[5];
    const float* w_o   = (const float*)d_in[6];
    const float* b_o   = (const float*)d_in[7];
    const float* ln2_g = (const float*)d_in[8];
    const float* ln2_b = (const float*)d_in[9];
    const float* w1    = (const float*)d_in[10];
    const float* b1    = (const float*)d_in[11];
    const float* w2    = (const float*)d_in[12];
    const float* b2    = (const float*)d_in[13];
    float* out = (float*)d_out;

    __half *h,*qkv,*att,*ffn,*wqkv,*wo,*w1t,*w2t;
    float *x1;
    cudaGetSymbolAddress((void**)&h,    g_h);
    cudaGetSymbolAddress((void**)&qkv,  g_qkv);
    cudaGetSymbolAddress((void**)&att,  g_att);
    cudaGetSymbolAddress((void**)&x1,   g_x1);
    cudaGetSymbolAddress((void**)&ffn,  g_ffn);
    cudaGetSymbolAddress((void**)&wqkv, g_wqkvT);
    cudaGetSymbolAddress((void**)&wo,   g_woT);
    cudaGetSymbolAddress((void**)&w1t,  g_w1T);
    cudaGetSymbolAddress((void**)&w2t,  g_w2T);

    cudaFuncSetAttribute(attn_mma, cudaFuncAttributeMaxDynamicSharedMemorySize, ATT_SMEM);
    cudaFuncSetAttribute(mma_gemm<0>, cudaFuncAttributeMaxDynamicSharedMemorySize, MG_SMEM);
    cudaFuncSetAttribute(mma_gemm<1>, cudaFuncAttributeMaxDynamicSharedMemorySize, MG_SMEM);
    cudaFuncSetAttribute(mma_gemm<2>, cudaFuncAttributeMaxDynamicSharedMemorySize, MG_SMEM);

    dim3 tb(32, 8);
    dim3 gP(DMODEL / 128, ROWS / 128);    // (8, 64)
    dim3 gF1(FFN_DIM / 128, ROWS / 128);  // (32, 64)

    // 1-4: weight transpose + fp16 quantize
    wsplitT<<<dim3(DMODEL/32, DMODEL/32), tb>>>(w_q, wqkv,                   DMODEL, DMODEL);
    wsplitT<<<dim3(DMODEL/32, DMODEL/32), tb>>>(w_k, wqkv + DMODEL*DMODEL,   DMODEL, DMODEL);
    wsplitT<<<dim3(DMODEL/32, DMODEL/32), tb>>>(w_v, wqkv + 2*DMODEL*DMODEL, DMODEL, DMODEL);
    wsplitT<<<dim3(DMODEL/32, DMODEL/32), tb>>>(w_o, wo,  DMODEL, DMODEL);
    // 5: LN1
    ln_kernel<<<ROWS, 256>>>(x, ln1_g, ln1_b, h);
    // 6 (ncu -s 5 -c 1 window): fused QKV projection -> fp16
    mma_gemm<0><<<dim3(QKV_N/128, ROWS/128), 256, MG_SMEM>>>(h, wqkv,
        nullptr, nullptr, nullptr, qkv, ROWS, QKV_N, DMODEL);
    // 7: tensor-core attention -> fp16
    attn_mma<<<dim3(SEQ / 64, BATCH * NHEAD), 128, ATT_SMEM>>>(qkv, att);
    // 8: O projection + bias + residual -> x1 (fp32)
    mma_gemm<1><<<gP, 256, MG_SMEM>>>(att, wo, b_o, x, x1, nullptr, ROWS, DMODEL, DMODEL);
    // 9: LN2
    ln_kernel<<<ROWS, 256>>>(x1, ln2_g, ln2_b, h);
    // 10: w1 split
    wsplitT<<<dim3(FFN_DIM/32, DMODEL/32), tb>>>(w1, w1t, DMODEL, FFN_DIM);
    // 11: FFN up + GELU -> fp16
    mma_gemm<2><<<gF1, 256, MG_SMEM>>>(h, w1t, b1, nullptr, nullptr, ffn, ROWS, FFN_DIM, DMODEL);
    // 12: w2 split
    wsplitT<<<dim3(DMODEL/32, FFN_DIM/32), tb>>>(w2, w2t, FFN_DIM, DMODEL);
    // 13: FFN down + bias + residual -> out
    mma_gemm<1><<<gP, 256, MG_SMEM>>>(ffn, w2t, b2, x1, out, nullptr, ROWS, DMODEL, FFN_DIM);
}

// round 7
// speedup vs baseline: 9.0741x; 1.0935x over previous
#include <cuda_runtime.h>
#include <cuda_fp16.h>
#include <math.h>
#include <stdint.h>

#define BATCH   16
#define SEQ     512
#define DMODEL  1024
#define NHEAD   16
#define DK      64
#define FFN_DIM 4096
#define ROWS    (BATCH * SEQ)        // 8192
#define QKV_N   (3 * DMODEL)         // 3072

// ---------------- scratch (device globals; no allocation) ----------------
__device__ __half g_h   [ROWS * DMODEL];
__device__ __half g_qkv [ROWS * QKV_N];
__device__ __half g_att [ROWS * DMODEL];
__device__ float  g_x1  [ROWS * DMODEL];
__device__ __half g_ffn [ROWS * FFN_DIM];
// transposed fp16 weights: T[N,K]
__device__ __half g_wqkvT[QKV_N*DMODEL];
__device__ __half g_woT  [DMODEL*DMODEL];
__device__ __half g_w1T  [DMODEL*FFN_DIM];
__device__ __half g_w2T  [FFN_DIM*DMODEL];

// ---------------- helpers ----------------
__device__ __forceinline__ uint32_t smem_u32(const void* p) {
    uint32_t a;
    asm("{ .reg .u64 t; cvta.to.shared.u64 t, %1; cvt.u32.u64 %0, t; }" : "=r"(a) : "l"(p));
    return a;
}
#define CP_ASYNC16(dst, src) \
    asm volatile("cp.async.cg.shared.global [%0], [%1], 16;" :: "r"(dst), "l"(src) : "memory")
#define CP_COMMIT() asm volatile("cp.async.commit_group;" ::: "memory")
#define CP_WAIT(n)  asm volatile("cp.async.wait_group %0;" :: "n"(n) : "memory")
#define SMEM_SWZ128(off) ((off) ^ (((off) >> 3) & 0x70))

__device__ __forceinline__ void ldsm_x4(uint32_t* r, uint32_t addr) {
    asm volatile("ldmatrix.sync.aligned.m8n8.x4.shared.b16 {%0,%1,%2,%3}, [%4];"
        : "=r"(r[0]), "=r"(r[1]), "=r"(r[2]), "=r"(r[3]) : "r"(addr));
}
__device__ __forceinline__ void ldsm_x4_t(uint32_t* r, uint32_t addr) {
    asm volatile("ldmatrix.sync.aligned.m8n8.x4.trans.shared.b16 {%0,%1,%2,%3}, [%4];"
        : "=r"(r[0]), "=r"(r[1]), "=r"(r[2]), "=r"(r[3]) : "r"(addr));
}
__device__ __forceinline__ void mma16816(float* d, const uint32_t* a, const uint32_t* b) {
    asm volatile("mma.sync.aligned.m16n8k16.row.col.f32.f16.f16.f32 "
        "{%0,%1,%2,%3}, {%4,%5,%6,%7}, {%8,%9}, {%0,%1,%2,%3};"
        : "+f"(d[0]), "+f"(d[1]), "+f"(d[2]), "+f"(d[3])
        : "r"(a[0]), "r"(a[1]), "r"(a[2]), "r"(a[3]), "r"(b[0]), "r"(b[1]));
}

__device__ __forceinline__ float gelu_exact(float v) {
    return 0.5f * v * (1.0f + erff(v * 0.70710678118654752f));
}
__device__ __forceinline__ uint32_t pack2h(__half a, __half b) {
    __half2 t(a, b);
    return *reinterpret_cast<uint32_t*>(&t);
}

// ---------------- fused weight transpose + fp16 quantize ----------------
// Packed 1-D tile index over multiple W[K,N] -> T[N,K] transposes (32x32 tiles).
struct WArgs {
    const float* W[3];
    __half*      T[3];
    int K[3], N[3], tiles[3];   // tiles[i] = (K/32)*(N/32)
};

__global__ void wsplit_all(WArgs a)
{
    __shared__ float t[32][33];
    int idx = blockIdx.x;
    int m = 0;
    if (idx >= a.tiles[0]) { idx -= a.tiles[0]; m = 1; }
    if (m == 1 && idx >= a.tiles[1]) { idx -= a.tiles[1]; m = 2; }
    const float* W = a.W[m];
    __half* T = a.T[m];
    int K = a.K[m], N = a.N[m];
    int ntx = N >> 5;
    int n0 = (idx % ntx) * 32, k0 = (idx / ntx) * 32;

    int tx = threadIdx.x, ty = threadIdx.y;
    #pragma unroll
    for (int i = 0; i < 4; i++)
        t[ty + 8*i][tx] = W[(size_t)(k0 + ty + 8*i) * N + n0 + tx];
    __syncthreads();
    #pragma unroll
    for (int i = 0; i < 4; i++) {
        size_t o = (size_t)(n0 + ty + 8*i) * K + k0 + tx;
        T[o] = __float2half(t[tx][ty + 8*i]);
    }
}

// ---------------- LayerNorm: one block per row, outputs fp16 ----------------
__global__ void ln_kernel(const float* __restrict__ x,
                          const float* __restrict__ g,
                          const float* __restrict__ b,
                          __half* __restrict__ oh)
{
    int row = blockIdx.x;
    const float4* xr = reinterpret_cast<const float4*>(x + (size_t)row * DMODEL);
    int t = threadIdx.x;
    float4 v = xr[t];
    float s  = v.x + v.y + v.z + v.w;
    float sq = v.x*v.x + v.y*v.y + v.z*v.z + v.w*v.w;

    __shared__ float red_s[8], red_q[8];
    for (int o = 16; o > 0; o >>= 1) {
        s  += __shfl_xor_sync(0xffffffffu, s,  o);
        sq += __shfl_xor_sync(0xffffffffu, sq, o);
    }
    int wid = t >> 5, lid = t & 31;
    if (lid == 0) { red_s[wid] = s; red_q[wid] = sq; }
    __syncthreads();
    if (wid == 0) {
        float ss = (lid < 8) ? red_s[lid] : 0.f;
        float qq = (lid < 8) ? red_q[lid] : 0.f;
        for (int o = 4; o > 0; o >>= 1) {
            ss += __shfl_xor_sync(0xffffffffu, ss, o);
            qq += __shfl_xor_sync(0xffffffffu, qq, o);
        }
        if (lid == 0) { red_s[0] = ss; red_q[0] = qq; }
    }
    __syncthreads();
    float mean = red_s[0] * (1.0f / DMODEL);
    float var  = red_q[0] * (1.0f / DMODEL) - mean * mean;
    float rstd = rsqrtf(var + 1e-5f);

    float4 gv = reinterpret_cast<const float4*>(g)[t];
    float4 bv = reinterpret_cast<const float4*>(b)[t];
    float o0 = (v.x - mean) * rstd * gv.x + bv.x;
    float o1 = (v.y - mean) * rstd * gv.y + bv.y;
    float o2 = (v.z - mean) * rstd * gv.z + bv.z;
    float o3 = (v.w - mean) * rstd * gv.w + bv.w;
    __half2* ph = reinterpret_cast<__half2*>(oh + (size_t)row * DMODEL);
    ph[t*2]   = __half2(__float2half(o0), __float2half(o1));
    ph[t*2+1] = __half2(__float2half(o2), __float2half(o3));
}

// ---------------- mma.sync fp16 1-pass GEMM (3-stage, 2 CTAs/SM) ----------------
// C[M,N] = A[M,K] @ B[N,K]^T
// CTA tile 128x128, KBLK=64, 8 warps (2 M x 4 N), warp tile 64x32.
// EPI: 0 = fp16 C; 1 = +bias +resid -> fp32 C; 2 = +bias, GELU -> fp16 C
#define KBLK 64
#define STAGE_BYTES 32768            // A 16K | B 16K
#define NSTAGE 3
#define MG_SMEM (NSTAGE * STAGE_BYTES)   // 98304

template<int EPI>
__global__ __launch_bounds__(256, 2)
void mma_gemm(const __half* __restrict__ A, const __half* __restrict__ B,
              const float* __restrict__ bias, const float* __restrict__ resid,
              float* __restrict__ C, __half* __restrict__ Ch,
              int M, int N, int K)
{
    extern __shared__ char sm[];
    uint32_t sb = smem_u32(sm);

    int tid  = threadIdx.x;
    int wid  = tid >> 5;
    int lane = tid & 31;
    int wm   = wid & 1;
    int wn   = wid >> 1;

    int row0 = blockIdx.y * 128, col0 = blockIdx.x * 128;
    const __half* pA = A + (size_t)row0 * K;
    const __half* pB = B + (size_t)col0 * K;

    int KB = K / KBLK;

    int ld_r[4], ld_c[4];
    uint32_t ld_so[4];
    #pragma unroll
    for (int i = 0; i < 4; i++) {
        int idx = tid + (i << 8);
        ld_r[i] = idx >> 3;
        ld_c[i] = idx & 7;
        ld_so[i] = SMEM_SWZ128((uint32_t)(ld_r[i] * 128 + ld_c[i] * 16));
    }

    auto stage_base = [&](int kb) {
        int s = kb % NSTAGE;
        return sb + (uint32_t)s * STAGE_BYTES;
    };

    auto load_stage = [&](int kb) {
        uint32_t base = stage_base(kb);
        int koff = kb * KBLK;
        #pragma unroll
        for (int i = 0; i < 4; i++) {
            size_t go = (size_t)ld_r[i] * K + koff + ld_c[i] * 8;
            CP_ASYNC16(base + ld_so[i],         (const void*)(pA + go));
            CP_ASYNC16(base + 16384 + ld_so[i], (const void*)(pB + go));
        }
        CP_COMMIT();
    };

    float acc[4][4][4];
    #pragma unroll
    for (int i = 0; i < 4; i++)
        #pragma unroll
        for (int j = 0; j < 4; j++)
            #pragma unroll
            for (int e = 0; e < 4; e++) acc[i][j][e] = 0.f;

    load_stage(0);
    load_stage(1);

    for (int kb = 0; kb < KB; kb++) {
        if (kb + 2 < KB) load_stage(kb + 2);
        else             CP_COMMIT();
        CP_WAIT(2);
        __syncthreads();

        uint32_t base = stage_base(kb);
        uint32_t sA = base, sB = base + 16384;

        #pragma unroll
        for (int kk = 0; kk < 4; kk++) {
            uint32_t ah[4][4], bh[4][2];
            int acol2 = (kk * 16 + ((lane >> 4) << 3)) * 2;
            #pragma unroll
            for (int mt = 0; mt < 4; mt++) {
                int row = wm * 64 + mt * 16 + (lane & 15);
                uint32_t off = SMEM_SWZ128((uint32_t)(row * 128 + acol2));
                ldsm_x4(ah[mt], sA + off);
            }
            int bcol2 = (kk * 16 + (((lane >> 3) & 1) << 3)) * 2;
            int brow  = wn * 32 + ((lane >> 4) << 3) + (lane & 7);
            #pragma unroll
            for (int p = 0; p < 2; p++) {
                uint32_t off = SMEM_SWZ128((uint32_t)((brow + p * 16) * 128 + bcol2));
                uint32_t t[4];
                ldsm_x4(t, sB + off);
                bh[p*2][0] = t[0]; bh[p*2][1] = t[1]; bh[p*2+1][0] = t[2]; bh[p*2+1][1] = t[3];
            }
            #pragma unroll
            for (int mt = 0; mt < 4; mt++)
                #pragma unroll
                for (int nt = 0; nt < 4; nt++)
                    mma16816(acc[mt][nt], ah[mt], bh[nt]);
        }
        __syncthreads();
    }

    // epilogue
    int g  = lane >> 2;
    int c2 = (lane & 3) * 2;
    #pragma unroll
    for (int mt = 0; mt < 4; mt++) {
        #pragma unroll
        for (int nt = 0; nt < 4; nt++) {
            int row = row0 + wm * 64 + mt * 16 + g;
            int col = col0 + wn * 32 + nt * 8 + c2;
            float d[4] = {acc[mt][nt][0], acc[mt][nt][1], acc[mt][nt][2], acc[mt][nt][3]};
            if (EPI >= 1) {
                float b0 = __ldg(&bias[col]), b1 = __ldg(&bias[col + 1]);
                d[0] += b0; d[1] += b1; d[2] += b0; d[3] += b1;
            }
            if (EPI == 1) {
                float2 r0 = *reinterpret_cast<const float2*>(&resid[(size_t)row * N + col]);
                float2 r1 = *reinterpret_cast<const float2*>(&resid[(size_t)(row + 8) * N + col]);
                d[0] += r0.x; d[1] += r0.y; d[2] += r1.x; d[3] += r1.y;
                *reinterpret_cast<float2*>(&C[(size_t)row * N + col])       = make_float2(d[0], d[1]);
                *reinterpret_cast<float2*>(&C[(size_t)(row + 8) * N + col]) = make_float2(d[2], d[3]);
            } else {
                if (EPI == 2) {
                    d[0] = gelu_exact(d[0]); d[1] = gelu_exact(d[1]);
                    d[2] = gelu_exact(d[2]); d[3] = gelu_exact(d[3]);
                }
                *reinterpret_cast<__half2*>(&Ch[(size_t)row * N + col]) =
                    __half2(__float2half(d[0]), __float2half(d[1]));
                *reinterpret_cast<__half2*>(&Ch[(size_t)(row + 8) * N + col]) =
                    __half2(__float2half(d[2]), __float2half(d[3]));
            }
        }
    }
}

// ---------------- tensor-core causal flash attention (fp16, 1-pass) ----------------
// CTA: 128 threads (4 warps), one (b, h, qtile64). Warp w owns q rows [16w, 16w+16).
// smem: sQ(8K) | stage s: K(8K) V(8K), 2 stages.
#define ATT_SMEM (8192 + 2 * 16384)   // 40960

__global__ __launch_bounds__(128, 4)
void attn_mma(const __half* __restrict__ QKV,
              __half* __restrict__ O)
{
    extern __shared__ char sm[];
    uint32_t sb = smem_u32(sm);
    int tid = threadIdx.x, lane = tid & 31, w = tid >> 5;
    int bh = blockIdx.y, b = bh >> 4, h = bh & 15;
    int qt = blockIdx.x;
    const int QS = QKV_N;   // 3072

    // ---- issue Q loads ----
    {
        size_t q0 = (size_t)(b * SEQ + qt * 64) * QS + h * DK;
        #pragma unroll
        for (int i = 0; i < 4; i++) {
            int idx = tid + (i << 7);
            int r = idx >> 3, c = idx & 7;
            uint32_t so = SMEM_SWZ128((uint32_t)(r * 128 + c * 16));
            CP_ASYNC16(sb + so, (const void*)(QKV + q0 + (size_t)r * QS + c * 8));
        }
    }

    auto load_kv = [&](int kt) {
        uint32_t base = sb + 8192 + (kt & 1) * 16384;
        size_t k0 = (size_t)(b * SEQ + kt * 64) * QS + h * DK + DMODEL;
        size_t v0 = k0 + DMODEL;
        #pragma unroll
        for (int i = 0; i < 4; i++) {
            int idx = tid + (i << 7);
            int r = idx >> 3, c = idx & 7;
            uint32_t so = SMEM_SWZ128((uint32_t)(r * 128 + c * 16));
            CP_ASYNC16(base + so,        (const void*)(QKV + k0 + (size_t)r * QS + c * 8));
            CP_ASYNC16(base + 8192 + so, (const void*)(QKV + v0 + (size_t)r * QS + c * 8));
        }
        CP_COMMIT();
    };

    load_kv(0);
    CP_WAIT(0);
    __syncthreads();

    // ---- hoist Q fragments ----
    uint32_t qh[4][4];
    {
        int arow = w * 16 + (lane & 15);
        #pragma unroll
        for (int s = 0; s < 4; s++) {
            uint32_t off = SMEM_SWZ128((uint32_t)(arow * 128 + (s * 16 + ((lane >> 4) << 3)) * 2));
            ldsm_x4(qh[s], sb + off);
        }
    }

    float oacc[8][4];
    #pragma unroll
    for (int i = 0; i < 8; i++)
        #pragma unroll
        for (int e = 0; e < 4; e++) oacc[i][e] = 0.f;
    float m0 = -1e30f, m1 = -1e30f, l0 = 0.f, l1 = 0.f;

    int r0g = qt * 64 + w * 16 + (lane >> 2);
    int r1g = r0g + 8;

    for (int kt = 0; kt <= qt; kt++) {
        if (kt > 0) { CP_WAIT(0); __syncthreads(); }
        if (kt < qt) load_kv(kt + 1);

        uint32_t kbase = sb + 8192 + (kt & 1) * 16384;
        uint32_t vbase = kbase + 8192;

        // ---- S = Q K^T ----
        float sacc[8][4];
        #pragma unroll
        for (int i = 0; i < 8; i++)
            #pragma unroll
            for (int e = 0; e < 4; e++) sacc[i][e] = 0.f;

        int b_r = ((lane >> 4) << 3) + (lane & 7);
        #pragma unroll
        for (int s = 0; s < 4; s++) {
            int b_c2 = (s * 16 + (((lane >> 3) & 1) << 3)) * 2;
            #pragma unroll
            for (int np = 0; np < 4; np++) {
                uint32_t off = SMEM_SWZ128((uint32_t)((np * 16 + b_r) * 128 + b_c2));
                uint32_t th[4];
                ldsm_x4(th, kbase + off);
                uint32_t kh0[2] = {th[0], th[1]}, kh1[2] = {th[2], th[3]};
                mma16816(sacc[2*np],   qh[s], kh0);
                mma16816(sacc[2*np+1], qh[s], kh1);
            }
        }

        // ---- scale + causal mask ----
        #pragma unroll
        for (int nt = 0; nt < 8; nt++)
            #pragma unroll
            for (int e = 0; e < 4; e++) sacc[nt][e] *= 0.125f;
        if (kt == qt) {
            #pragma unroll
            for (int nt = 0; nt < 8; nt++) {
                int colb = kt * 64 + nt * 8 + 2 * (lane & 3);
                #pragma unroll
                for (int e = 0; e < 2; e++) {
                    if (colb + e > r0g) sacc[nt][e]     = -1e30f;
                    if (colb + e > r1g) sacc[nt][2 + e] = -1e30f;
                }
            }
        }

        // ---- online softmax ----
        float mx0 = sacc[0][0], mx1 = sacc[0][2];
        #pragma unroll
        for (int nt = 0; nt < 8; nt++) {
            mx0 = fmaxf(mx0, fmaxf(sacc[nt][0], sacc[nt][1]));
            mx1 = fmaxf(mx1, fmaxf(sacc[nt][2], sacc[nt][3]));
        }
        mx0 = fmaxf(mx0, __shfl_xor_sync(0xffffffffu, mx0, 1));
        mx0 = fmaxf(mx0, __shfl_xor_sync(0xffffffffu, mx0, 2));
        mx1 = fmaxf(mx1, __shfl_xor_sync(0xffffffffu, mx1, 1));
        mx1 = fmaxf(mx1, __shfl_xor_sync(0xffffffffu, mx1, 2));
        float mn0 = fmaxf(m0, mx0), mn1 = fmaxf(m1, mx1);
        float a0 = __expf(m0 - mn0), a1 = __expf(m1 - mn1);

        float sum0 = 0.f, sum1 = 0.f;
        #pragma unroll
        for (int nt = 0; nt < 8; nt++) {
            sacc[nt][0] = __expf(sacc[nt][0] - mn0);
            sacc[nt][1] = __expf(sacc[nt][1] - mn0);
            sacc[nt][2] = __expf(sacc[nt][2] - mn1);
            sacc[nt][3] = __expf(sacc[nt][3] - mn1);
            sum0 += sacc[nt][0] + sacc[nt][1];
            sum1 += sacc[nt][2] + sacc[nt][3];
        }
        sum0 += __shfl_xor_sync(0xffffffffu, sum0, 1);
        sum0 += __shfl_xor_sync(0xffffffffu, sum0, 2);
        sum1 += __shfl_xor_sync(0xffffffffu, sum1, 1);
        sum1 += __shfl_xor_sync(0xffffffffu, sum1, 2);
        l0 = l0 * a0 + sum0;  m0 = mn0;
        l1 = l1 * a1 + sum1;  m1 = mn1;
        #pragma unroll
        for (int nt = 0; nt < 8; nt++) {
            oacc[nt][0] *= a0; oacc[nt][1] *= a0;
            oacc[nt][2] *= a1; oacc[nt][3] *= a1;
        }

        // ---- O += P V ----
        int r_in = lane & 7, sel = lane >> 3;
        #pragma unroll
        for (int s = 0; s < 4; s++) {
            uint32_t pah[4];
            #pragma unroll
            for (int half = 0; half < 2; half++) {
                float* pv = sacc[2*s + half];
                pah[half*2]   = pack2h(__float2half(pv[0]), __float2half(pv[1]));
                pah[half*2+1] = pack2h(__float2half(pv[2]), __float2half(pv[3]));
            }
            int vrow = s * 16 + (sel & 1) * 8 + r_in;
            #pragma unroll
            for (int np = 0; np < 4; np++) {
                int cb = np * 32 + (sel >> 1) * 16;
                uint32_t off = SMEM_SWZ128((uint32_t)(vrow * 128 + cb));
                uint32_t vh[4];
                ldsm_x4_t(vh, vbase + off);
                uint32_t vh0[2] = {vh[0], vh[1]}, vh1[2] = {vh[2], vh[3]};
                mma16816(oacc[2*np],   pah, vh0);
                mma16816(oacc[2*np+1], pah, vh1);
            }
        }
    }

    // ---- epilogue: O /= l, write fp16 ----
    float inv0 = 1.0f / l0, inv1 = 1.0f / l1;
    int grow = b * SEQ + r0g;
    #pragma unroll
    for (int nt = 0; nt < 8; nt++) {
        int col = h * DK + nt * 8 + 2 * (lane & 3);
        *reinterpret_cast<__half2*>(&O[(size_t)grow * DMODEL + col]) =
            __half2(__float2half(oacc[nt][0] * inv0), __float2half(oacc[nt][1] * inv0));
        *reinterpret_cast<__half2*>(&O[(size_t)(grow + 8) * DMODEL + col]) =
            __half2(__float2half(oacc[nt][2] * inv1), __float2half(oacc[nt][3] * inv1));
    }
}

// ---------------- launch ----------------
extern "C" void kernel_launch(void* const* d_in, const int* in_sizes, int n_in,
                              void* d_out, int out_size)
{
    const float* x     = (const float*)d_in[0];
    const float* ln1_g = (const float*)d_in[1];
    const float* ln1_b = (const float*)d_in[2];
    const float* w_q   = (const float*)d_in[3];
    const float* w_k   = (const float*)d_in[4];
    const float* w_v   = (const float*)d_in[5];
    const float* w_o   = (const float*)d_in[6];
    const float* b_o   = (const float*)d_in[7];
    const float* ln2_g = (const float*)d_in[8];
    const float* ln2_b = (const float*)d_in[9];
    const float* w1    = (const float*)d_in[10];
    const float* b1    = (const float*)d_in[11];
    const float* w2    = (const float*)d_in[12];
    const float* b2    = (const float*)d_in[13];
    float* out = (float*)d_out;

    __half *h,*qkv,*att,*ffn,*wqkv,*wo,*w1t,*w2t;
    float *x1;
    cudaGetSymbolAddress((void**)&h,    g_h);
    cudaGetSymbolAddress((void**)&qkv,  g_qkv);
    cudaGetSymbolAddress((void**)&att,  g_att);
    cudaGetSymbolAddress((void**)&x1,   g_x1);
    cudaGetSymbolAddress((void**)&ffn,  g_ffn);
    cudaGetSymbolAddress((void**)&wqkv, g_wqkvT);
    cudaGetSymbolAddress((void**)&wo,   g_woT);
    cudaGetSymbolAddress((void**)&w1t,  g_w1T);
    cudaGetSymbolAddress((void**)&w2t,  g_w2T);

    cudaFuncSetAttribute(attn_mma, cudaFuncAttributeMaxDynamicSharedMemorySize, ATT_SMEM);
    cudaFuncSetAttribute(mma_gemm<0>, cudaFuncAttributeMaxDynamicSharedMemorySize, MG_SMEM);
    cudaFuncSetAttribute(mma_gemm<1>, cudaFuncAttributeMaxDynamicSharedMemorySize, MG_SMEM);
    cudaFuncSetAttribute(mma_gemm<2>, cudaFuncAttributeMaxDynamicSharedMemorySize, MG_SMEM);

    dim3 tb(32, 8);
    dim3 gP(DMODEL / 128, ROWS / 128);    // (8, 64)
    dim3 gF1(FFN_DIM / 128, ROWS / 128);  // (32, 64)

    // ---- Launch 1: QKV weight transpose+quantize (3 matrices, 3072 tiles) ----
    {
        WArgs a;
        a.W[0] = w_q; a.T[0] = wqkv;
        a.W[1] = w_k; a.T[1] = wqkv + DMODEL*DMODEL;
        a.W[2] = w_v; a.T[2] = wqkv + 2*DMODEL*DMODEL;
        for (int i = 0; i < 3; i++) { a.K[i] = DMODEL; a.N[i] = DMODEL; a.tiles[i] = 1024; }
        wsplit_all<<<3072, tb>>>(a);
    }
    // ---- Launch 2: LN1 ----
    ln_kernel<<<ROWS, 256>>>(x, ln1_g, ln1_b, h);
    // ---- Launch 3: remaining weight transposes (wo, w1, w2; 9216 tiles) ----
    {
        WArgs a;
        a.W[0] = w_o; a.T[0] = wo;  a.K[0] = DMODEL;  a.N[0] = DMODEL;  a.tiles[0] = 1024;
        a.W[1] = w1;  a.T[1] = w1t; a.K[1] = DMODEL;  a.N[1] = FFN_DIM; a.tiles[1] = 4096;
        a.W[2] = w2;  a.T[2] = w2t; a.K[2] = FFN_DIM; a.N[2] = DMODEL;  a.tiles[2] = 4096;
        wsplit_all<<<9216, tb>>>(a);
    }
    // ---- Launch 4 (profiled): fused QKV projection -> fp16 ----
    mma_gemm<0><<<dim3(QKV_N/128, ROWS/128), 256, MG_SMEM>>>(h, wqkv,
        nullptr, nullptr, nullptr, qkv, ROWS, QKV_N, DMODEL);
    // ---- Launch 5: tensor-core attention -> fp16 ----
    attn_mma<<<dim3(SEQ / 64, BATCH * NHEAD), 128, ATT_SMEM>>>(qkv, att);
    // ---- Launch 6: O projection + bias + residual -> x1 (fp32) ----
    mma_gemm<1><<<gP, 256, MG_SMEM>>>(att, wo, b_o, x, x1, nullptr, ROWS, DMODEL, DMODEL);
    // ---- Launch 7: LN2 ----
    ln_kernel<<<ROWS, 256>>>(x1, ln2_g, ln2_b, h);
    // ---- Launch 8: FFN up + GELU -> fp16 ----
    mma_gemm<2><<<gF1, 256, MG_SMEM>>>(h, w1t, b1, nullptr, nullptr, ffn, ROWS, FFN_DIM, DMODEL);
    // ---- Launch 9: FFN down + bias + residual -> out ----
    mma_gemm<1><<<gP, 256, MG_SMEM>>>(ffn, w2t, b2, x1, out, nullptr, ROWS, DMODEL, FFN_DIM);
}